// round 2
// baseline (speedup 1.0000x reference)
#include <cuda_runtime.h>

typedef unsigned long long ull;

constexpr int B_ = 2, T_ = 2048, C_ = 1024, H_ = 16, D_ = 64;
constexpr int BT_ = B_ * T_;   // 4096
constexpr int BH_ = B_ * H_;   // 32

// ---------------- scratch (static device arrays; no allocation allowed) ----
__device__ float g_q [BT_ * C_];
__device__ float g_k [BT_ * C_];
__device__ float g_v [BT_ * C_];
__device__ float g_qn[BT_ * C_];   // [BH][T][D]
__device__ float g_kn[BT_ * C_];   // [BH][T][D]
__device__ float g_vn[BT_ * C_];   // [BH][T][D]
__device__ float g_att[BT_ * C_];  // [BT][C]

// ---------------- f32x2 helpers (FFMA2: 2 fp32 MACs / instruction) --------
__device__ __forceinline__ void fma2(ull& c, ull a, ull b) {
    asm("fma.rn.f32x2 %0, %1, %2, %3;" : "=l"(c) : "l"(a), "l"(b), "l"(c));
}
__device__ __forceinline__ ull mul2(ull a, ull b) {
    ull r; asm("mul.rn.f32x2 %0, %1, %2;" : "=l"(r) : "l"(a), "l"(b)); return r;
}
__device__ __forceinline__ ull dup2(float x) {
    ull r; asm("mov.b64 %0, {%1, %1};" : "=l"(r) : "f"(x)); return r;
}
__device__ __forceinline__ float2 unpack2(ull v) {
    float lo, hi; asm("mov.b64 {%0, %1}, %2;" : "=f"(lo), "=f"(hi) : "l"(v));
    return make_float2(lo, hi);
}

// ==========================================================================
// GEMM:  C[m,n] = sum_k A[m,k] * W[n,k]   (A row-major [M,K], W row-major [N,K])
// M=4096, N=1024, K=1024.  blockIdx.z selects one of up to 3 (W, out) pairs
// so the three QKV GEMMs run as one 768-block launch (full-chip occupancy).
// BM=BN=128, BK=16, 256 threads, 8x8 outputs/thread via f32x2 (4x8 u64 accs).
// ==========================================================================
__global__ void __launch_bounds__(256) gemm_nt_kernel(
    const float* __restrict__ A,
    const float* __restrict__ W0, const float* __restrict__ W1, const float* __restrict__ W2,
    float* __restrict__ O0, float* __restrict__ O1, float* __restrict__ O2)
{
    constexpr int N = C_, K = C_;
    constexpr int BM = 128, BN = 128, BK = 16;

    const float* W = (blockIdx.z == 0) ? W0 : ((blockIdx.z == 1) ? W1 : W2);
    float*       O = (blockIdx.z == 0) ? O0 : ((blockIdx.z == 1) ? O1 : O2);

    __shared__ float As[BK][BM];   // stored transposed: As[k][m]
    __shared__ float Bs[BK][BN];   // Bs[k][n]

    const int tid = threadIdx.x;
    const int tx  = tid & 15;      // N direction (8 cols each)
    const int ty  = tid >> 4;      // M direction (8 rows each)
    const int lr  = tid >> 2;      // load row 0..63
    const int lc  = (tid & 3) << 2;// load col 0,4,8,12

    const float* Ab = A + (size_t)blockIdx.y * BM * K;
    const float* Wb = W + (size_t)blockIdx.x * BN * K;

    ull acc[4][8];
#pragma unroll
    for (int i = 0; i < 4; i++)
#pragma unroll
        for (int j = 0; j < 8; j++) acc[i][j] = 0ull;

    for (int k0 = 0; k0 < K; k0 += BK) {
#pragma unroll
        for (int rr = 0; rr < 2; rr++) {
            const int row = lr + rr * 64;
            float4 va = *(const float4*)(Ab + (size_t)row * K + k0 + lc);
            As[lc + 0][row] = va.x; As[lc + 1][row] = va.y;
            As[lc + 2][row] = va.z; As[lc + 3][row] = va.w;
            float4 vb = *(const float4*)(Wb + (size_t)row * K + k0 + lc);
            Bs[lc + 0][row] = vb.x; Bs[lc + 1][row] = vb.y;
            Bs[lc + 2][row] = vb.z; Bs[lc + 3][row] = vb.w;
        }
        __syncthreads();
#pragma unroll
        for (int kk = 0; kk < BK; kk++) {
            // a pairs: rows (ty*8+2i, ty*8+2i+1) packed directly from smem
            ulonglong2 a01 = *(const ulonglong2*)&As[kk][ty * 8];
            ulonglong2 a23 = *(const ulonglong2*)&As[kk][ty * 8 + 4];
            float4 b0 = *(const float4*)&Bs[kk][tx * 8];
            float4 b1 = *(const float4*)&Bs[kk][tx * 8 + 4];
            ull ap[4] = { a01.x, a01.y, a23.x, a23.y };
            ull bd[8] = { dup2(b0.x), dup2(b0.y), dup2(b0.z), dup2(b0.w),
                          dup2(b1.x), dup2(b1.y), dup2(b1.z), dup2(b1.w) };
#pragma unroll
            for (int i = 0; i < 4; i++)
#pragma unroll
                for (int j = 0; j < 8; j++)
                    fma2(acc[i][j], ap[i], bd[j]);
        }
        __syncthreads();
    }

    const int crow0 = blockIdx.y * BM + ty * 8;
    const int ccol  = blockIdx.x * BN + tx * 8;
#pragma unroll
    for (int i = 0; i < 4; i++) {
        float r0[8], r1[8];
#pragma unroll
        for (int j = 0; j < 8; j++) {
            float2 f = unpack2(acc[i][j]);
            r0[j] = f.x; r1[j] = f.y;
        }
        float* p0 = O + (size_t)(crow0 + 2 * i + 0) * N + ccol;
        float* p1 = O + (size_t)(crow0 + 2 * i + 1) * N + ccol;
        *(float4*)(p0)     = make_float4(r0[0], r0[1], r0[2], r0[3]);
        *(float4*)(p0 + 4) = make_float4(r0[4], r0[5], r0[6], r0[7]);
        *(float4*)(p1)     = make_float4(r1[0], r1[1], r1[2], r1[3]);
        *(float4*)(p1 + 4) = make_float4(r1[4], r1[5], r1[6], r1[7]);
    }
}

// ==========================================================================
// RoPE (interleaved pairs) + L2 norm + scale, and relayout to [BH][T][D].
// One warp per (b,t,h) row; lane p owns elements (2p, 2p+1) = one rope pair.
// sqrt(D)=8 attention scale is folded into q.
// ==========================================================================
__global__ void __launch_bounds__(256) rope_norm_kernel(
    const float* __restrict__ tq, const float* __restrict__ tk, const float* __restrict__ tv,
    const float* __restrict__ sqk,
    float* __restrict__ Qn, float* __restrict__ Kn, float* __restrict__ Vn)
{
    const int gw   = (blockIdx.x * blockDim.x + threadIdx.x) >> 5; // 0 .. BT*H-1
    const int lane = threadIdx.x & 31;
    const int h  = gw & (H_ - 1);
    const int bt = gw >> 4;          // H=16
    const int t  = bt & (T_ - 1);
    const int b  = bt >> 11;         // T=2048
    const int p  = lane;             // pair index 0..31

    const size_t src = (size_t)bt * C_ + h * D_ + 2 * p;
    float2 q2 = *(const float2*)(tq + src);
    float2 k2 = *(const float2*)(tk + src);
    float2 v2 = *(const float2*)(tv + src);

    // inv_freq[p] = 10000^(-(2p)/64); angle = t * inv_freq  (matches ref fp32 path)
    const float ex   = -((float)(2 * p) / (float)D_) * 13.287712379549449f; // log2(10000)
    const float invf = exp2f(ex);
    float sn, cs;
    sincosf((float)t * invf, &sn, &cs);

    float2 qr, kr;
    qr.x = q2.x * cs - q2.y * sn;  qr.y = q2.y * cs + q2.x * sn;
    kr.x = k2.x * cs - k2.y * sn;  kr.y = k2.y * cs + k2.x * sn;

    float qs = qr.x * qr.x + qr.y * qr.y;
    float ks = kr.x * kr.x + kr.y * kr.y;
#pragma unroll
    for (int o = 16; o > 0; o >>= 1) {
        qs += __shfl_xor_sync(0xffffffffu, qs, o);
        ks += __shfl_xor_sync(0xffffffffu, ks, o);
    }
    const float qn = fmaxf(sqrtf(qs), 1e-12f);
    const float kn = fmaxf(sqrtf(ks), 1e-12f);

    float2 sc = *(const float2*)(sqk + h * D_ + 2 * p);
    const float iq = (32.0f * 8.0f) / qn;   // scale 32, sqrt(D)=8 folded into q
    const float ik = 32.0f / kn;

    const size_t dst = (((size_t)(b * H_ + h)) * T_ + t) * D_ + 2 * p;
    *(float2*)(Qn + dst) = make_float2(qr.x * iq * sc.x, qr.y * iq * sc.y);
    *(float2*)(Kn + dst) = make_float2(kr.x * ik * sc.x, kr.y * ik * sc.y);
    *(float2*)(Vn + dst) = v2;
}

// ==========================================================================
// Flash attention, fp32, f32x2 inner loops.
// Grid (T/64, B*H). Block 256 threads: thread = (row r = tid/4, quad q4 = tid&3).
// Quad q4 owns keys {q4 + 4*jj} (interleaved -> conflict-free K LDS) and
// output d-chunks {q4 + 4*cc} (interleaved -> conflict-free V LDS).
// smem rows padded to stride 68 (16B-aligned, bank-spread).
// ==========================================================================
constexpr int PAD = 68;

__global__ void __launch_bounds__(256) attn_kernel(
    const float* __restrict__ Qn, const float* __restrict__ Kn,
    const float* __restrict__ Vn, float* __restrict__ Y)
{
    extern __shared__ float sm[];
    float* Qs = sm;                    // 64 x PAD
    float* Ks = Qs + 64 * PAD;         // 64 x PAD
    float* Vs = Ks + 64 * PAD;         // 64 x PAD
    float* Ps = Vs + 64 * PAD;         // 64 x PAD

    const int tid = threadIdx.x;
    const int r   = tid >> 2;          // query row in tile 0..63
    const int q4  = tid & 3;           // quad

    const int bh = blockIdx.y;
    const int qt = blockIdx.x;

    const float* Qg = Qn + ((size_t)bh * T_ + qt * 64) * D_;   // contiguous 4096 floats
    const float* Kg0 = Kn + (size_t)bh * T_ * D_;
    const float* Vg0 = Vn + (size_t)bh * T_ * D_;

    // load Q tile
#pragma unroll
    for (int i = 0; i < 4; i++) {
        const int idx = tid + i * 256;
        const int row = idx >> 4, c = (idx & 15) << 2;
        *(float4*)(Qs + row * PAD + c) = *(const float4*)(Qg + row * 64 + c);
    }

    float m_run = -3.0e38f, l_run = 0.0f;
    ull o2[8];
#pragma unroll
    for (int i = 0; i < 8; i++) o2[i] = 0ull;

    for (int kt = 0; kt < T_ / 64; kt++) {
        const float* Kg = Kg0 + (size_t)kt * 64 * D_;
        const float* Vg = Vg0 + (size_t)kt * 64 * D_;

        __syncthreads();   // previous tile fully consumed (also orders Q load on kt==0)
#pragma unroll
        for (int i = 0; i < 4; i++) {
            const int idx = tid + i * 256;
            const int row = idx >> 4, c = (idx & 15) << 2;
            *(float4*)(Ks + row * PAD + c) = *(const float4*)(Kg + row * 64 + c);
            *(float4*)(Vs + row * PAD + c) = *(const float4*)(Vg + row * 64 + c);
        }
        __syncthreads();

        // ---- S = Q . K^T  (keys q4+4*jj), f32x2 over D ----
        ull s2[16];
#pragma unroll
        for (int jj = 0; jj < 16; jj++) s2[jj] = 0ull;

        const float* qrow = Qs + r * PAD;
#pragma unroll 4
        for (int d4 = 0; d4 < 16; d4++) {
            ulonglong2 qv = *(const ulonglong2*)(qrow + d4 * 4);
#pragma unroll
            for (int jj = 0; jj < 16; jj++) {
                ulonglong2 kv = *(const ulonglong2*)(Ks + (q4 + 4 * jj) * PAD + d4 * 4);
                fma2(s2[jj], qv.x, kv.x);
                fma2(s2[jj], qv.y, kv.y);
            }
        }
        float s[16];
#pragma unroll
        for (int jj = 0; jj < 16; jj++) {
            float2 f = unpack2(s2[jj]);
            s[jj] = f.x + f.y;
        }

        // ---- online softmax (row owned by a lane-quad within one warp) ----
        float mt = s[0];
#pragma unroll
        for (int jj = 1; jj < 16; jj++) mt = fmaxf(mt, s[jj]);
        mt = fmaxf(mt, __shfl_xor_sync(0xffffffffu, mt, 1));
        mt = fmaxf(mt, __shfl_xor_sync(0xffffffffu, mt, 2));
        const float m_new = fmaxf(m_run, mt);
        const float alpha = __expf(m_run - m_new);

        float psum = 0.0f;
        float* prow = Ps + r * PAD;
#pragma unroll
        for (int jj = 0; jj < 16; jj++) {
            const float p = __expf(s[jj] - m_new);
            psum += p;
            prow[q4 + 4 * jj] = p;
        }
        psum += __shfl_xor_sync(0xffffffffu, psum, 1);
        psum += __shfl_xor_sync(0xffffffffu, psum, 2);
        l_run = l_run * alpha + psum;
        m_run = m_new;

        const ull a2 = dup2(alpha);
#pragma unroll
        for (int i = 0; i < 8; i++) o2[i] = mul2(o2[i], a2);

        __syncwarp();      // Ps producer/consumer are the same warp

        // ---- O += P . V   (d-chunks q4+4*cc) ----
#pragma unroll 8
        for (int j = 0; j < 64; j++) {
            const ull p2 = dup2(prow[j]);
            const float* vrow = Vs + j * PAD;
#pragma unroll
            for (int cc = 0; cc < 4; cc++) {
                ulonglong2 v = *(const ulonglong2*)(vrow + (q4 + 4 * cc) * 4);
                fma2(o2[2 * cc + 0], p2, v.x);
                fma2(o2[2 * cc + 1], p2, v.y);
            }
        }
    }

    // ---- epilogue: O / l, write to [BT][C] layout for the Wo GEMM ----
    const float inv_l = 1.0f / l_run;
    const int b = bh >> 4, h = bh & 15;
    float* dst = Y + ((size_t)b * T_ + qt * 64 + r) * C_ + h * D_;
#pragma unroll
    for (int cc = 0; cc < 4; cc++) {
        float2 f0 = unpack2(o2[2 * cc + 0]);
        float2 f1 = unpack2(o2[2 * cc + 1]);
        *(float4*)(dst + (q4 + 4 * cc) * 4) =
            make_float4(f0.x * inv_l, f0.y * inv_l, f1.x * inv_l, f1.y * inv_l);
    }
}

// ==========================================================================
extern "C" void kernel_launch(void* const* d_in, const int* in_sizes, int n_in,
                              void* d_out, int out_size)
{
    const float* x   = (const float*)d_in[0];
    const float* Wq  = (const float*)d_in[1];
    const float* Wk  = (const float*)d_in[2];
    const float* Wv  = (const float*)d_in[3];
    const float* Wo  = (const float*)d_in[4];
    const float* sqk = (const float*)d_in[5];
    float* out = (float*)d_out;

    // Resolve scratch addresses / attributes once (host-side, deterministic,
    // no device-memory effect) so repeated graph captures see only launches.
    static float *q = nullptr, *k, *v, *qn, *kn, *vn, *att;
    static bool init_done = false;
    if (!init_done) {
        cudaGetSymbolAddress((void**)&q,   g_q);
        cudaGetSymbolAddress((void**)&k,   g_k);
        cudaGetSymbolAddress((void**)&v,   g_v);
        cudaGetSymbolAddress((void**)&qn,  g_qn);
        cudaGetSymbolAddress((void**)&kn,  g_kn);
        cudaGetSymbolAddress((void**)&vn,  g_vn);
        cudaGetSymbolAddress((void**)&att, g_att);
        cudaFuncSetAttribute(attn_kernel,
                             cudaFuncAttributeMaxDynamicSharedMemorySize,
                             (int)((size_t)4 * 64 * PAD * sizeof(float)));
        init_done = true;
    }

    // QKV projections: one launch, 3 GEMMs via grid.z
    dim3 gqkv(C_ / 128, BT_ / 128, 3);
    gemm_nt_kernel<<<gqkv, 256>>>(x, Wq, Wk, Wv, q, k, v);

    // RoPE + norm + relayout
    rope_norm_kernel<<<(BT_ * H_) / 8, 256>>>(q, k, v, sqk, qn, kn, vn);

    // Flash attention
    const size_t smem = (size_t)4 * 64 * PAD * sizeof(float);   // 69632 B
    attn_kernel<<<dim3(T_ / 64, BH_), 256, smem>>>(qn, kn, vn, att);

    // Output projection
    dim3 go(C_ / 128, BT_ / 128, 1);
    gemm_nt_kernel<<<go, 256>>>(att, Wo, Wo, Wo, out, out, out);
}

// round 6
// speedup vs baseline: 1.4803x; 1.4803x over previous
#include <cuda_runtime.h>

typedef unsigned long long ull;

constexpr int B_ = 2, T_ = 2048, C_ = 1024, H_ = 16, D_ = 64;
constexpr int BT_ = B_ * T_;   // 4096
constexpr int BH_ = B_ * H_;   // 32

// ---------------- scratch (static device arrays; no allocation allowed) ----
__device__ float g_q [BT_ * C_];
__device__ float g_k [BT_ * C_];
__device__ float g_v [BT_ * C_];
__device__ float g_qn[BT_ * C_];   // [BH][T][D]
__device__ float g_kn[BT_ * C_];   // [BH][T][D]
__device__ float g_vn[BT_ * C_];   // [BH][T][D]
__device__ float g_att[BT_ * C_];  // [BT][C]

// ---------------- f32x2 helpers (FFMA2: 2 fp32 MACs / instruction) --------
__device__ __forceinline__ void fma2(ull& c, ull a, ull b) {
    asm("fma.rn.f32x2 %0, %1, %2, %3;" : "=l"(c) : "l"(a), "l"(b), "l"(c));
}
__device__ __forceinline__ ull mul2(ull a, ull b) {
    ull r; asm("mul.rn.f32x2 %0, %1, %2;" : "=l"(r) : "l"(a), "l"(b)); return r;
}
__device__ __forceinline__ ull dup2(float x) {
    ull r; asm("mov.b64 %0, {%1, %1};" : "=l"(r) : "f"(x)); return r;
}
__device__ __forceinline__ float2 unpack2(ull v) {
    float lo, hi; asm("mov.b64 {%0, %1}, %2;" : "=f"(lo), "=f"(hi) : "l"(v));
    return make_float2(lo, hi);
}

// ==========================================================================
// GEMM:  C[m,n] = sum_k A[m,k] * W[n,k]
// M=4096, N=K=1024.  grid.z selects one of 3 (W, out) pairs.
// BM=BN=128, BK=16, 256 threads, 8x8 outputs/thread (m-pair packed f32x2).
// B stored in smem PRE-DUPLICATED as f32x2 pairs -> zero dup-MOVs in loop.
// Double-buffered smem with register prefetch; one syncthreads per BK tile.
// ==========================================================================
__global__ void __launch_bounds__(256, 2) gemm_nt_kernel(
    const float* __restrict__ A,
    const float* __restrict__ W0, const float* __restrict__ W1, const float* __restrict__ W2,
    float* __restrict__ O0, float* __restrict__ O1, float* __restrict__ O2)
{
    constexpr int N = C_, K = C_;
    constexpr int BM = 128, BN = 128, BK = 16;
    constexpr int NT = K / BK;   // 64

    const float* W = (blockIdx.z == 0) ? W0 : ((blockIdx.z == 1) ? W1 : W2);
    float*       O = (blockIdx.z == 0) ? O0 : ((blockIdx.z == 1) ? O1 : O2);

    __shared__ float As [2][BK][BM];   // As[buf][k][m]           (8 KB x2)
    __shared__ ull   Bsd[2][BK][BN];   // dup pairs: (b,b) per n  (16 KB x2)

    const int tid = threadIdx.x;
    const int tx  = tid & 15;          // N direction
    const int ty  = tid >> 4;          // M direction (8 rows)
    const int lr  = tid >> 2;          // loader row 0..63
    const int lc  = (tid & 3) << 2;    // loader col 0,4,8,12

    const float* pA0 = A + (size_t)(blockIdx.y * BM + lr) * K + lc;
    const float* pA1 = pA0 + (size_t)64 * K;
    const float* pW0 = W + (size_t)(blockIdx.x * BN + lr) * K + lc;
    const float* pW1 = pW0 + (size_t)64 * K;

    ull acc[4][8];
#pragma unroll
    for (int i = 0; i < 4; i++)
#pragma unroll
        for (int j = 0; j < 8; j++) acc[i][j] = 0ull;

    float4 va0, va1, vb0, vb1;

    // prologue load tile 0
    va0 = *(const float4*)(pA0); va1 = *(const float4*)(pA1);
    vb0 = *(const float4*)(pW0); vb1 = *(const float4*)(pW1);
    {
        As[0][lc+0][lr] = va0.x; As[0][lc+1][lr] = va0.y; As[0][lc+2][lr] = va0.z; As[0][lc+3][lr] = va0.w;
        As[0][lc+0][lr+64] = va1.x; As[0][lc+1][lr+64] = va1.y; As[0][lc+2][lr+64] = va1.z; As[0][lc+3][lr+64] = va1.w;
        Bsd[0][lc+0][lr] = dup2(vb0.x); Bsd[0][lc+1][lr] = dup2(vb0.y);
        Bsd[0][lc+2][lr] = dup2(vb0.z); Bsd[0][lc+3][lr] = dup2(vb0.w);
        Bsd[0][lc+0][lr+64] = dup2(vb1.x); Bsd[0][lc+1][lr+64] = dup2(vb1.y);
        Bsd[0][lc+2][lr+64] = dup2(vb1.z); Bsd[0][lc+3][lr+64] = dup2(vb1.w);
    }
    __syncthreads();

    for (int t = 0; t < NT; ++t) {
        const int buf = t & 1;
        if (t + 1 < NT) {
            const int k0 = (t + 1) * BK;
            va0 = *(const float4*)(pA0 + k0); va1 = *(const float4*)(pA1 + k0);
            vb0 = *(const float4*)(pW0 + k0); vb1 = *(const float4*)(pW1 + k0);
        }
#pragma unroll
        for (int kk = 0; kk < BK; ++kk) {
            ulonglong2 a01 = *(const ulonglong2*)&As[buf][kk][ty * 8];
            ulonglong2 a23 = *(const ulonglong2*)&As[buf][kk][ty * 8 + 4];
            ulonglong2 b0 = *(const ulonglong2*)&Bsd[buf][kk][2 * tx];
            ulonglong2 b1 = *(const ulonglong2*)&Bsd[buf][kk][2 * tx + 32];
            ulonglong2 b2 = *(const ulonglong2*)&Bsd[buf][kk][2 * tx + 64];
            ulonglong2 b3 = *(const ulonglong2*)&Bsd[buf][kk][2 * tx + 96];
            ull ap[4] = { a01.x, a01.y, a23.x, a23.y };
            ull bd[8] = { b0.x, b0.y, b1.x, b1.y, b2.x, b2.y, b3.x, b3.y };
#pragma unroll
            for (int i = 0; i < 4; i++)
#pragma unroll
                for (int j = 0; j < 8; j++)
                    fma2(acc[i][j], ap[i], bd[j]);
        }
        if (t + 1 < NT) {
            const int nb = (t + 1) & 1;
            As[nb][lc+0][lr] = va0.x; As[nb][lc+1][lr] = va0.y; As[nb][lc+2][lr] = va0.z; As[nb][lc+3][lr] = va0.w;
            As[nb][lc+0][lr+64] = va1.x; As[nb][lc+1][lr+64] = va1.y; As[nb][lc+2][lr+64] = va1.z; As[nb][lc+3][lr+64] = va1.w;
            Bsd[nb][lc+0][lr] = dup2(vb0.x); Bsd[nb][lc+1][lr] = dup2(vb0.y);
            Bsd[nb][lc+2][lr] = dup2(vb0.z); Bsd[nb][lc+3][lr] = dup2(vb0.w);
            Bsd[nb][lc+0][lr+64] = dup2(vb1.x); Bsd[nb][lc+1][lr+64] = dup2(vb1.y);
            Bsd[nb][lc+2][lr+64] = dup2(vb1.z); Bsd[nb][lc+3][lr+64] = dup2(vb1.w);
            __syncthreads();
        }
    }

    // epilogue: rows = by*128 + ty*8 + 2i (+0/1 lo/hi); cols n = 2tx + 32g (+0/1)
    const int crow0 = blockIdx.y * BM + ty * 8;
    const int ccol  = blockIdx.x * BN + 2 * tx;
#pragma unroll
    for (int i = 0; i < 4; i++) {
        float* p0 = O + (size_t)(crow0 + 2 * i + 0) * N + ccol;
        float* p1 = O + (size_t)(crow0 + 2 * i + 1) * N + ccol;
#pragma unroll
        for (int g = 0; g < 4; g++) {
            float2 f0 = unpack2(acc[i][2 * g]);
            float2 f1 = unpack2(acc[i][2 * g + 1]);
            *(float2*)(p0 + 32 * g) = make_float2(f0.x, f1.x);
            *(float2*)(p1 + 32 * g) = make_float2(f0.y, f1.y);
        }
    }
}

// ==========================================================================
// RoPE (interleaved pairs) + L2 norm + scale, relayout to [BH][T][D].
// ==========================================================================
__global__ void __launch_bounds__(256) rope_norm_kernel(
    const float* __restrict__ tq, const float* __restrict__ tk, const float* __restrict__ tv,
    const float* __restrict__ sqk,
    float* __restrict__ Qn, float* __restrict__ Kn, float* __restrict__ Vn)
{
    const int gw   = (blockIdx.x * blockDim.x + threadIdx.x) >> 5;
    const int lane = threadIdx.x & 31;
    const int h  = gw & (H_ - 1);
    const int bt = gw >> 4;
    const int t  = bt & (T_ - 1);
    const int b  = bt >> 11;
    const int p  = lane;

    const size_t src = (size_t)bt * C_ + h * D_ + 2 * p;
    float2 q2 = *(const float2*)(tq + src);
    float2 k2 = *(const float2*)(tk + src);
    float2 v2 = *(const float2*)(tv + src);

    const float ex   = -((float)(2 * p) / (float)D_) * 13.287712379549449f;
    const float invf = exp2f(ex);
    float sn, cs;
    sincosf((float)t * invf, &sn, &cs);

    float2 qr, kr;
    qr.x = q2.x * cs - q2.y * sn;  qr.y = q2.y * cs + q2.x * sn;
    kr.x = k2.x * cs - k2.y * sn;  kr.y = k2.y * cs + k2.x * sn;

    float qs = qr.x * qr.x + qr.y * qr.y;
    float ks = kr.x * kr.x + kr.y * kr.y;
#pragma unroll
    for (int o = 16; o > 0; o >>= 1) {
        qs += __shfl_xor_sync(0xffffffffu, qs, o);
        ks += __shfl_xor_sync(0xffffffffu, ks, o);
    }
    const float qn = fmaxf(sqrtf(qs), 1e-12f);
    const float kn = fmaxf(sqrtf(ks), 1e-12f);

    float2 sc = *(const float2*)(sqk + h * D_ + 2 * p);
    const float iq = (32.0f * 8.0f) / qn;   // s_qk scale 32, sqrt(D)=8 folded in q
    const float ik = 32.0f / kn;

    const size_t dst = (((size_t)(b * H_ + h)) * T_ + t) * D_ + 2 * p;
    *(float2*)(Qn + dst) = make_float2(qr.x * iq * sc.x, qr.y * iq * sc.y);
    *(float2*)(Kn + dst) = make_float2(kr.x * ik * sc.x, kr.y * ik * sc.y);
    *(float2*)(Vn + dst) = v2;
}

// ==========================================================================
// Flash attention v2: 64x64 tiles, 256 threads, thread (i=tid>>4, j=tid&15)
// owns 4 q-rows (4i..4i+3), 4 strided keys (j+16s), 4 d-cols (4j..4j+3).
// P stored in smem PRE-DUPLICATED as f32x2 -> PV is 3 LDS.128 + 8 FFMA2/key.
// ==========================================================================
constexpr int PAD = 68;        // floats per smem row (16B-aligned, bank-spread)
constexpr int PP  = 66;        // ull pitch of Pd rows (16B-aligned)

__global__ void __launch_bounds__(256, 2) attn_kernel(
    const float* __restrict__ Qn, const float* __restrict__ Kn,
    const float* __restrict__ Vn, float* __restrict__ Y)
{
    extern __shared__ float sm[];
    float* Qs = sm;                       // 64 x PAD
    float* Ks = Qs + 64 * PAD;            // 64 x PAD
    float* Vs = Ks + 64 * PAD;            // 64 x PAD
    ull*   Pd = (ull*)(Vs + 64 * PAD);    // 64 keys x PP ull (dup pairs by row)

    const int tid = threadIdx.x;
    const int i   = tid >> 4;             // row group 0..15  (rows 4i..4i+3)
    const int j   = tid & 15;             // key lane / d-col group

    const int bh = blockIdx.y;
    const int qt = blockIdx.x;

    const float* Qg  = Qn + ((size_t)bh * T_ + qt * 64) * D_;
    const float* Kg0 = Kn + (size_t)bh * T_ * D_;
    const float* Vg0 = Vn + (size_t)bh * T_ * D_;

    // load Q tile
#pragma unroll
    for (int u = 0; u < 4; u++) {
        const int idx = tid + u * 256;
        const int row = idx >> 4, c = (idx & 15) << 2;
        *(float4*)(Qs + row * PAD + c) = *(const float4*)(Qg + row * 64 + c);
    }

    float m_run[4], l_run[4];
    ull o2[4][2];
#pragma unroll
    for (int r = 0; r < 4; r++) {
        m_run[r] = -3.0e38f; l_run[r] = 0.0f;
        o2[r][0] = 0ull; o2[r][1] = 0ull;
    }

    for (int kt = 0; kt < T_ / 64; kt++) {
        const float* Kg = Kg0 + (size_t)kt * 64 * D_;
        const float* Vg = Vg0 + (size_t)kt * 64 * D_;

        __syncthreads();   // prior tile fully consumed (covers Q load on kt==0)
#pragma unroll
        for (int u = 0; u < 4; u++) {
            const int idx = tid + u * 256;
            const int row = idx >> 4, c = (idx & 15) << 2;
            *(float4*)(Ks + row * PAD + c) = *(const float4*)(Kg + row * 64 + c);
            *(float4*)(Vs + row * PAD + c) = *(const float4*)(Vg + row * 64 + c);
        }
        __syncthreads();

        // ---- S = Q.K^T : 4 rows x 4 keys, f32x2 along d ----
        ull s2[4][4];
#pragma unroll
        for (int r = 0; r < 4; r++)
#pragma unroll
            for (int s = 0; s < 4; s++) s2[r][s] = 0ull;

#pragma unroll 4
        for (int d4 = 0; d4 < 16; d4++) {
            ulonglong2 qv[4], kv[4];
#pragma unroll
            for (int r = 0; r < 4; r++)
                qv[r] = *(const ulonglong2*)(Qs + (4 * i + r) * PAD + 4 * d4);
#pragma unroll
            for (int s = 0; s < 4; s++)
                kv[s] = *(const ulonglong2*)(Ks + (j + 16 * s) * PAD + 4 * d4);
#pragma unroll
            for (int r = 0; r < 4; r++)
#pragma unroll
                for (int s = 0; s < 4; s++) {
                    fma2(s2[r][s], qv[r].x, kv[s].x);
                    fma2(s2[r][s], qv[r].y, kv[s].y);
                }
        }

        // ---- online softmax (stats replicated across the 16 j-lanes) ----
        float p4[4][4];
#pragma unroll
        for (int r = 0; r < 4; r++) {
            float s[4];
#pragma unroll
            for (int ss = 0; ss < 4; ss++) {
                float2 f = unpack2(s2[r][ss]);
                s[ss] = f.x + f.y;
            }
            float mt = fmaxf(fmaxf(s[0], s[1]), fmaxf(s[2], s[3]));
            mt = fmaxf(mt, __shfl_xor_sync(0xffffffffu, mt, 1, 16));
            mt = fmaxf(mt, __shfl_xor_sync(0xffffffffu, mt, 2, 16));
            mt = fmaxf(mt, __shfl_xor_sync(0xffffffffu, mt, 4, 16));
            mt = fmaxf(mt, __shfl_xor_sync(0xffffffffu, mt, 8, 16));
            const float m_new = fmaxf(m_run[r], mt);
            const float alpha = __expf(m_run[r] - m_new);
            float psum = 0.0f;
#pragma unroll
            for (int ss = 0; ss < 4; ss++) {
                const float p = __expf(s[ss] - m_new);
                p4[r][ss] = p;
                psum += p;
            }
            psum += __shfl_xor_sync(0xffffffffu, psum, 1, 16);
            psum += __shfl_xor_sync(0xffffffffu, psum, 2, 16);
            psum += __shfl_xor_sync(0xffffffffu, psum, 4, 16);
            psum += __shfl_xor_sync(0xffffffffu, psum, 8, 16);
            l_run[r] = l_run[r] * alpha + psum;
            m_run[r] = m_new;
            const ull a2 = dup2(alpha);
            o2[r][0] = mul2(o2[r][0], a2);
            o2[r][1] = mul2(o2[r][1], a2);
        }

        // ---- write P dup-pairs; produced & consumed by the SAME warp ----
#pragma unroll
        for (int ss = 0; ss < 4; ss++) {
            ull* pr = Pd + (size_t)(j + 16 * ss) * PP + 4 * i;
            pr[0] = dup2(p4[0][ss]); pr[1] = dup2(p4[1][ss]);
            pr[2] = dup2(p4[2][ss]); pr[3] = dup2(p4[3][ss]);
        }
        __syncwarp();

        // ---- O += P.V : per key 2 LDS.128 (P-dups) + 1 LDS.128 (V) + 8 FFMA2
#pragma unroll 4
        for (int k = 0; k < 64; k++) {
            ulonglong2 pa = *(const ulonglong2*)(Pd + (size_t)k * PP + 4 * i);      // rows 4i,4i+1
            ulonglong2 pb = *(const ulonglong2*)(Pd + (size_t)k * PP + 4 * i + 2);  // rows 4i+2,4i+3
            ulonglong2 vv = *(const ulonglong2*)(Vs + k * PAD + 4 * j);             // d = 4j..4j+3
            fma2(o2[0][0], pa.x, vv.x); fma2(o2[0][1], pa.x, vv.y);
            fma2(o2[1][0], pa.y, vv.x); fma2(o2[1][1], pa.y, vv.y);
            fma2(o2[2][0], pb.x, vv.x); fma2(o2[2][1], pb.x, vv.y);
            fma2(o2[3][0], pb.y, vv.x); fma2(o2[3][1], pb.y, vv.y);
        }
    }

    // ---- epilogue: O / l, write to [BT][C] for the Wo GEMM ----
    const int b = bh >> 4, h = bh & 15;
#pragma unroll
    for (int r = 0; r < 4; r++) {
        const float il = 1.0f / l_run[r];
        float2 f0 = unpack2(o2[r][0]);
        float2 f1 = unpack2(o2[r][1]);
        float* dst = Y + ((size_t)b * T_ + qt * 64 + 4 * i + r) * C_ + h * D_ + 4 * j;
        *(float4*)dst = make_float4(f0.x * il, f0.y * il, f1.x * il, f1.y * il);
    }
}

// ==========================================================================
extern "C" void kernel_launch(void* const* d_in, const int* in_sizes, int n_in,
                              void* d_out, int out_size)
{
    const float* x   = (const float*)d_in[0];
    const float* Wq  = (const float*)d_in[1];
    const float* Wk  = (const float*)d_in[2];
    const float* Wv  = (const float*)d_in[3];
    const float* Wo  = (const float*)d_in[4];
    const float* sqk = (const float*)d_in[5];
    float* out = (float*)d_out;

    static float *q = nullptr, *k, *v, *qn, *kn, *vn, *att;
    static bool init_done = false;
    const size_t attn_smem = (size_t)3 * 64 * PAD * sizeof(float) + (size_t)64 * PP * 8;
    if (!init_done) {
        cudaGetSymbolAddress((void**)&q,   g_q);
        cudaGetSymbolAddress((void**)&k,   g_k);
        cudaGetSymbolAddress((void**)&v,   g_v);
        cudaGetSymbolAddress((void**)&qn,  g_qn);
        cudaGetSymbolAddress((void**)&kn,  g_kn);
        cudaGetSymbolAddress((void**)&vn,  g_vn);
        cudaGetSymbolAddress((void**)&att, g_att);
        cudaFuncSetAttribute(attn_kernel,
                             cudaFuncAttributeMaxDynamicSharedMemorySize, (int)attn_smem);
        init_done = true;
    }

    dim3 gqkv(C_ / 128, BT_ / 128, 3);
    gemm_nt_kernel<<<gqkv, 256>>>(x, Wq, Wk, Wv, q, k, v);

    rope_norm_kernel<<<(BT_ * H_) / 8, 256>>>(q, k, v, sqk, qn, kn, vn);

    attn_kernel<<<dim3(T_ / 64, BH_), 256, attn_smem>>>(qn, kn, vn, att);

    dim3 go(C_ / 128, BT_ / 128, 1);
    gemm_nt_kernel<<<go, 256>>>(att, Wo, Wo, Wo, out, out, out);
}

// round 10
// speedup vs baseline: 2.1161x; 1.4295x over previous
#include <cuda_runtime.h>
#include <cuda_bf16.h>
#include <cstdint>

typedef unsigned long long ull;

constexpr int B_ = 2, T_ = 2048, C_ = 1024, H_ = 16, D_ = 64;
constexpr int BT_ = B_ * T_;   // 4096
constexpr int BH_ = B_ * H_;   // 32
constexpr int AELEM = BT_ * C_;      // 4194304
constexpr int WELEM = C_ * C_;       // 1048576

// ---------------- scratch (static device arrays; no allocation allowed) ----
__device__ float g_q [BT_ * C_];
__device__ float g_k [BT_ * C_];
__device__ float g_v [BT_ * C_];
__device__ float g_qn[BT_ * C_];   // [BH][T][D]
__device__ float g_kn[BT_ * C_];   // [BH][T][D]
__device__ float g_vn[BT_ * C_];   // [BH][T][D]
__device__ float g_att[BT_ * C_];  // [BT][C]

__device__ __nv_bfloat16 g_xs [2 * AELEM];      // x  split: hi | lo
__device__ __nv_bfloat16 g_ws [4 * 2 * WELEM];  // Wq,Wk,Wv,Wo: per-matrix hi | lo
__device__ __nv_bfloat16 g_as [2 * AELEM];      // att split: hi | lo

// ---------------- f32x2 helpers (FFMA2) -----------------------------------
__device__ __forceinline__ void fma2(ull& c, ull a, ull b) {
    asm("fma.rn.f32x2 %0, %1, %2, %3;" : "=l"(c) : "l"(a), "l"(b), "l"(c));
}
__device__ __forceinline__ ull mul2(ull a, ull b) {
    ull r; asm("mul.rn.f32x2 %0, %1, %2;" : "=l"(r) : "l"(a), "l"(b)); return r;
}
__device__ __forceinline__ ull dup2(float x) {
    ull r; asm("mov.b64 %0, {%1, %1};" : "=l"(r) : "f"(x)); return r;
}
__device__ __forceinline__ float2 unpack2(ull v) {
    float lo, hi; asm("mov.b64 {%0, %1}, %2;" : "=f"(lo), "=f"(hi) : "l"(v));
    return make_float2(lo, hi);
}
__device__ __forceinline__ uint32_t smem_u32(const void* p) {
    uint32_t a;
    asm("{ .reg .u64 t; cvta.to.shared.u64 t, %1; cvt.u32.u64 %0, t; }" : "=r"(a) : "l"(p));
    return a;
}

// ==========================================================================
// Split fp32 -> bf16 (hi) + bf16(residual) (lo).  4 elements / thread.
// ==========================================================================
__global__ void __launch_bounds__(256) split_kernel(
    const float4* __restrict__ in, uint2* __restrict__ hi, uint2* __restrict__ lo)
{
    const int i = blockIdx.x * blockDim.x + threadIdx.x;
    float4 f = in[i];
    uint32_t h0, h1;
    asm("cvt.rn.bf16x2.f32 %0, %1, %2;" : "=r"(h0) : "f"(f.y), "f"(f.x));
    asm("cvt.rn.bf16x2.f32 %0, %1, %2;" : "=r"(h1) : "f"(f.w), "f"(f.z));
    float r0 = f.x - __uint_as_float(h0 << 16);
    float r1 = f.y - __uint_as_float(h0 & 0xffff0000u);
    float r2 = f.z - __uint_as_float(h1 << 16);
    float r3 = f.w - __uint_as_float(h1 & 0xffff0000u);
    uint32_t l0, l1;
    asm("cvt.rn.bf16x2.f32 %0, %1, %2;" : "=r"(l0) : "f"(r1), "f"(r0));
    asm("cvt.rn.bf16x2.f32 %0, %1, %2;" : "=r"(l1) : "f"(r3), "f"(r2));
    hi[i] = make_uint2(h0, h1);
    lo[i] = make_uint2(l0, l1);
}

// W splitter: grid.z selects which W; outputs into g_ws + z*2*WELEM.
__global__ void __launch_bounds__(256) split_w_kernel(
    const float* __restrict__ W0, const float* __restrict__ W1,
    const float* __restrict__ W2, const float* __restrict__ W3,
    __nv_bfloat16* __restrict__ ws)
{
    const float* W = (blockIdx.z == 0) ? W0 : (blockIdx.z == 1) ? W1
                   : (blockIdx.z == 2) ? W2 : W3;
    const int i = blockIdx.x * blockDim.x + threadIdx.x;
    float4 f = ((const float4*)W)[i];
    uint32_t h0, h1;
    asm("cvt.rn.bf16x2.f32 %0, %1, %2;" : "=r"(h0) : "f"(f.y), "f"(f.x));
    asm("cvt.rn.bf16x2.f32 %0, %1, %2;" : "=r"(h1) : "f"(f.w), "f"(f.z));
    float r0 = f.x - __uint_as_float(h0 << 16);
    float r1 = f.y - __uint_as_float(h0 & 0xffff0000u);
    float r2 = f.z - __uint_as_float(h1 << 16);
    float r3 = f.w - __uint_as_float(h1 & 0xffff0000u);
    uint32_t l0, l1;
    asm("cvt.rn.bf16x2.f32 %0, %1, %2;" : "=r"(l0) : "f"(r1), "f"(r0));
    asm("cvt.rn.bf16x2.f32 %0, %1, %2;" : "=r"(l1) : "f"(r3), "f"(r2));
    uint2* hi = (uint2*)(ws + (size_t)blockIdx.z * 2 * WELEM);
    uint2* lo = (uint2*)(ws + (size_t)blockIdx.z * 2 * WELEM + WELEM);
    hi[i] = make_uint2(h0, h1);
    lo[i] = make_uint2(l0, l1);
}

// ==========================================================================
// HMMA GEMM (mma.sync m16n8k16 bf16):  O[m,n] = sum_k A[m,k] * W[n,k]
// bf16x3 split precision: acc = Ah*Bh + Ah*Bl + Al*Bh   (err ~2^-17)
// CTA 128x128, 8 warps (2m x 4n -> 64x32 warp tiles), K-stage = 32.
// smem: 2 buffers x 4 planes (Ah,Al,Bh,Bl) x 128 rows x 40 bf16 stride.
// cp.async double-buffered.  grid.z selects one of up to 3 (W,O) pairs.
// ==========================================================================
constexpr int GST   = 40;                    // smem row stride (bf16)
constexpr int PLANE = 128 * GST * 2;         // 10240 B
constexpr int GBUF  = 4 * PLANE;             // 40960 B
constexpr int GSMEM = 2 * GBUF;              // 81920 B

#define CPA16(dst, src) \
    asm volatile("cp.async.cg.shared.global [%0], [%1], 16;" :: "r"(dst), "l"(src))
#define CPA_COMMIT() asm volatile("cp.async.commit_group;" ::: "memory")

#define LDM_X4(r0, r1, r2, r3, a) \
    asm volatile("ldmatrix.sync.aligned.m8n8.x4.shared.b16 {%0,%1,%2,%3}, [%4];" \
                 : "=r"(r0), "=r"(r1), "=r"(r2), "=r"(r3) : "r"(a))

#define MMA16816(c, a, b) \
    asm volatile("mma.sync.aligned.m16n8k16.row.col.f32.bf16.bf16.f32 " \
                 "{%0,%1,%2,%3}, {%4,%5,%6,%7}, {%8,%9}, {%0,%1,%2,%3};" \
                 : "+f"((c)[0]), "+f"((c)[1]), "+f"((c)[2]), "+f"((c)[3]) \
                 : "r"((a)[0]), "r"((a)[1]), "r"((a)[2]), "r"((a)[3]), \
                   "r"((b)[0]), "r"((b)[1]))

__global__ void __launch_bounds__(256) gemm_hmma_kernel(
    const __nv_bfloat16* __restrict__ As,    // A hi at 0, lo at +AELEM
    const __nv_bfloat16* __restrict__ Ws,    // per-z: hi at z*2*WELEM, lo +WELEM
    float* __restrict__ O0, float* __restrict__ O1, float* __restrict__ O2)
{
    extern __shared__ char smem[];
    const uint32_t sb = smem_u32(smem);
    const int tid  = threadIdx.x;
    const int wid  = tid >> 5, lane = tid & 31;
    const int m0   = blockIdx.y * 128;
    const int n0   = blockIdx.x * 128;
    const int wm   = (wid & 1) * 64;          // warp m offset
    const int wn   = (wid >> 1) * 32;         // warp n offset

    float* O = (blockIdx.z == 0) ? O0 : ((blockIdx.z == 1) ? O1 : O2);
    const __nv_bfloat16* Ah = As;
    const __nv_bfloat16* Al = As + AELEM;
    const __nv_bfloat16* Bh = Ws + (size_t)blockIdx.z * 2 * WELEM;
    const __nv_bfloat16* Bl = Bh + WELEM;

    // loader: 2 chunks of 8 bf16 per plane per thread
    const int lrow = tid >> 2;                 // base row for chunk tid (0..63)
    const int lk8  = (tid & 3) * 8;            // k element offset 0,8,16,24

    float acc[4][4][4];
#pragma unroll
    for (int i = 0; i < 4; i++)
#pragma unroll
        for (int j = 0; j < 4; j++)
#pragma unroll
            for (int c = 0; c < 4; c++) acc[i][j][c] = 0.0f;

    // ldmatrix per-lane base addresses (bytes, within a buffer)
    const uint32_t aBase = (uint32_t)((wm + (lane & 15)) * (GST * 2) + (lane >> 4) * 16);
    const uint32_t bBase = (uint32_t)((wn + (lane & 7) + ((lane >> 4) & 1) * 8) * (GST * 2)
                                      + ((lane >> 3) & 1) * 16);

    auto issue_stage = [&](int kt, int buf) {
        const int k0 = kt * 32;
        const uint32_t dbase = sb + buf * GBUF;
#pragma unroll
        for (int h = 0; h < 2; h++) {
            const int row = lrow + h * 64;
            const uint32_t doff = (uint32_t)(row * (GST * 2) + lk8 * 2);
            const __nv_bfloat16* a_h = Ah + (size_t)(m0 + row) * 1024 + k0 + lk8;
            const __nv_bfloat16* a_l = Al + (size_t)(m0 + row) * 1024 + k0 + lk8;
            const __nv_bfloat16* b_h = Bh + (size_t)(n0 + row) * 1024 + k0 + lk8;
            const __nv_bfloat16* b_l = Bl + (size_t)(n0 + row) * 1024 + k0 + lk8;
            CPA16(dbase + 0 * PLANE + doff, a_h);
            CPA16(dbase + 1 * PLANE + doff, a_l);
            CPA16(dbase + 2 * PLANE + doff, b_h);
            CPA16(dbase + 3 * PLANE + doff, b_l);
        }
        CPA_COMMIT();
    };

    issue_stage(0, 0);

    for (int kt = 0; kt < 32; ++kt) {
        const int buf = kt & 1;
        if (kt + 1 < 32) {
            issue_stage(kt + 1, (kt + 1) & 1);
            asm volatile("cp.async.wait_group 1;" ::: "memory");
        } else {
            asm volatile("cp.async.wait_group 0;" ::: "memory");
        }
        __syncthreads();

        const uint32_t bbase = sb + buf * GBUF;
#pragma unroll
        for (int k16 = 0; k16 < 2; ++k16) {
            const uint32_t ko = (uint32_t)(k16 * 32);
            uint32_t ah[4][4], al[4][4];
#pragma unroll
            for (int i = 0; i < 4; i++) {
                LDM_X4(ah[i][0], ah[i][1], ah[i][2], ah[i][3],
                       bbase + 0 * PLANE + aBase + i * (16 * GST * 2) + ko);
                LDM_X4(al[i][0], al[i][1], al[i][2], al[i][3],
                       bbase + 1 * PLANE + aBase + i * (16 * GST * 2) + ko);
            }
            uint32_t bh[4][2], bl[4][2];
#pragma unroll
            for (int j2 = 0; j2 < 2; j2++) {
                uint32_t r0, r1, r2, r3;
                LDM_X4(r0, r1, r2, r3,
                       bbase + 2 * PLANE + bBase + j2 * (16 * GST * 2) + ko);
                bh[2 * j2][0] = r0; bh[2 * j2][1] = r1;
                bh[2 * j2 + 1][0] = r2; bh[2 * j2 + 1][1] = r3;
                LDM_X4(r0, r1, r2, r3,
                       bbase + 3 * PLANE + bBase + j2 * (16 * GST * 2) + ko);
                bl[2 * j2][0] = r0; bl[2 * j2][1] = r1;
                bl[2 * j2 + 1][0] = r2; bl[2 * j2 + 1][1] = r3;
            }
#pragma unroll
            for (int i = 0; i < 4; i++)
#pragma unroll
                for (int j = 0; j < 4; j++) {
                    MMA16816(acc[i][j], ah[i], bh[j]);
                    MMA16816(acc[i][j], ah[i], bl[j]);
                    MMA16816(acc[i][j], al[i], bh[j]);
                }
        }
        __syncthreads();
    }

    // epilogue
    const int r0 = lane >> 2, c0 = (lane & 3) * 2;
#pragma unroll
    for (int i = 0; i < 4; i++) {
#pragma unroll
        for (int j = 0; j < 4; j++) {
            float* p = O + (size_t)(m0 + wm + i * 16 + r0) * 1024 + n0 + wn + j * 8 + c0;
            *(float2*)p = make_float2(acc[i][j][0], acc[i][j][1]);
            *(float2*)(p + 8 * 1024) = make_float2(acc[i][j][2], acc[i][j][3]);
        }
    }
}

// ==========================================================================
// RoPE (interleaved pairs) + L2 norm + scale, relayout to [BH][T][D].
// ==========================================================================
__global__ void __launch_bounds__(256) rope_norm_kernel(
    const float* __restrict__ tq, const float* __restrict__ tk, const float* __restrict__ tv,
    const float* __restrict__ sqk,
    float* __restrict__ Qn, float* __restrict__ Kn, float* __restrict__ Vn)
{
    const int gw   = (blockIdx.x * blockDim.x + threadIdx.x) >> 5;
    const int lane = threadIdx.x & 31;
    const int h  = gw & (H_ - 1);
    const int bt = gw >> 4;
    const int t  = bt & (T_ - 1);
    const int b  = bt >> 11;
    const int p  = lane;

    const size_t src = (size_t)bt * C_ + h * D_ + 2 * p;
    float2 q2 = *(const float2*)(tq + src);
    float2 k2 = *(const float2*)(tk + src);
    float2 v2 = *(const float2*)(tv + src);

    const float ex   = -((float)(2 * p) / (float)D_) * 13.287712379549449f;
    const float invf = exp2f(ex);
    float sn, cs;
    sincosf((float)t * invf, &sn, &cs);

    float2 qr, kr;
    qr.x = q2.x * cs - q2.y * sn;  qr.y = q2.y * cs + q2.x * sn;
    kr.x = k2.x * cs - k2.y * sn;  kr.y = k2.y * cs + k2.x * sn;

    float qs = qr.x * qr.x + qr.y * qr.y;
    float ks = kr.x * kr.x + kr.y * kr.y;
#pragma unroll
    for (int o = 16; o > 0; o >>= 1) {
        qs += __shfl_xor_sync(0xffffffffu, qs, o);
        ks += __shfl_xor_sync(0xffffffffu, ks, o);
    }
    const float qn = fmaxf(sqrtf(qs), 1e-12f);
    const float kn = fmaxf(sqrtf(ks), 1e-12f);

    float2 sc = *(const float2*)(sqk + h * D_ + 2 * p);
    const float iq = (32.0f * 8.0f) / qn;   // s_qk scale 32, sqrt(D)=8 folded in q
    const float ik = 32.0f / kn;

    const size_t dst = (((size_t)(b * H_ + h)) * T_ + t) * D_ + 2 * p;
    *(float2*)(Qn + dst) = make_float2(qr.x * iq * sc.x, qr.y * iq * sc.y);
    *(float2*)(Kn + dst) = make_float2(kr.x * ik * sc.x, kr.y * ik * sc.y);
    *(float2*)(Vn + dst) = v2;
}

// ==========================================================================
// Flash attention (fp32, FFMA2): 64x64 tiles, 256 threads, thread (i, j)
// owns 4 q-rows, 4 strided keys, 4 d-cols.  P stored pre-duplicated f32x2.
// ==========================================================================
constexpr int PAD = 68;
constexpr int PP  = 66;

__global__ void __launch_bounds__(256, 2) attn_kernel(
    const float* __restrict__ Qn, const float* __restrict__ Kn,
    const float* __restrict__ Vn, float* __restrict__ Y)
{
    extern __shared__ float sm[];
    float* Qs = sm;
    float* Ks = Qs + 64 * PAD;
    float* Vs = Ks + 64 * PAD;
    ull*   Pd = (ull*)(Vs + 64 * PAD);

    const int tid = threadIdx.x;
    const int i   = tid >> 4;
    const int j   = tid & 15;

    const int bh = blockIdx.y;
    const int qt = blockIdx.x;

    const float* Qg  = Qn + ((size_t)bh * T_ + qt * 64) * D_;
    const float* Kg0 = Kn + (size_t)bh * T_ * D_;
    const float* Vg0 = Vn + (size_t)bh * T_ * D_;

#pragma unroll
    for (int u = 0; u < 4; u++) {
        const int idx = tid + u * 256;
        const int row = idx >> 4, c = (idx & 15) << 2;
        *(float4*)(Qs + row * PAD + c) = *(const float4*)(Qg + row * 64 + c);
    }

    float m_run[4], l_run[4];
    ull o2[4][2];
#pragma unroll
    for (int r = 0; r < 4; r++) {
        m_run[r] = -3.0e38f; l_run[r] = 0.0f;
        o2[r][0] = 0ull; o2[r][1] = 0ull;
    }

    for (int kt = 0; kt < T_ / 64; kt++) {
        const float* Kg = Kg0 + (size_t)kt * 64 * D_;
        const float* Vg = Vg0 + (size_t)kt * 64 * D_;

        __syncthreads();
#pragma unroll
        for (int u = 0; u < 4; u++) {
            const int idx = tid + u * 256;
            const int row = idx >> 4, c = (idx & 15) << 2;
            *(float4*)(Ks + row * PAD + c) = *(const float4*)(Kg + row * 64 + c);
            *(float4*)(Vs + row * PAD + c) = *(const float4*)(Vg + row * 64 + c);
        }
        __syncthreads();

        ull s2[4][4];
#pragma unroll
        for (int r = 0; r < 4; r++)
#pragma unroll
            for (int s = 0; s < 4; s++) s2[r][s] = 0ull;

#pragma unroll 4
        for (int d4 = 0; d4 < 16; d4++) {
            ulonglong2 qv[4], kv[4];
#pragma unroll
            for (int r = 0; r < 4; r++)
                qv[r] = *(const ulonglong2*)(Qs + (4 * i + r) * PAD + 4 * d4);
#pragma unroll
            for (int s = 0; s < 4; s++)
                kv[s] = *(const ulonglong2*)(Ks + (j + 16 * s) * PAD + 4 * d4);
#pragma unroll
            for (int r = 0; r < 4; r++)
#pragma unroll
                for (int s = 0; s < 4; s++) {
                    fma2(s2[r][s], qv[r].x, kv[s].x);
                    fma2(s2[r][s], qv[r].y, kv[s].y);
                }
        }

        float p4[4][4];
#pragma unroll
        for (int r = 0; r < 4; r++) {
            float s[4];
#pragma unroll
            for (int ss = 0; ss < 4; ss++) {
                float2 f = unpack2(s2[r][ss]);
                s[ss] = f.x + f.y;
            }
            float mt = fmaxf(fmaxf(s[0], s[1]), fmaxf(s[2], s[3]));
            mt = fmaxf(mt, __shfl_xor_sync(0xffffffffu, mt, 1, 16));
            mt = fmaxf(mt, __shfl_xor_sync(0xffffffffu, mt, 2, 16));
            mt = fmaxf(mt, __shfl_xor_sync(0xffffffffu, mt, 4, 16));
            mt = fmaxf(mt, __shfl_xor_sync(0xffffffffu, mt, 8, 16));
            const float m_new = fmaxf(m_run[r], mt);
            const float alpha = __expf(m_run[r] - m_new);
            float psum = 0.0f;
#pragma unroll
            for (int ss = 0; ss < 4; ss++) {
                const float p = __expf(s[ss] - m_new);
                p4[r][ss] = p;
                psum += p;
            }
            psum += __shfl_xor_sync(0xffffffffu, psum, 1, 16);
            psum += __shfl_xor_sync(0xffffffffu, psum, 2, 16);
            psum += __shfl_xor_sync(0xffffffffu, psum, 4, 16);
            psum += __shfl_xor_sync(0xffffffffu, psum, 8, 16);
            l_run[r] = l_run[r] * alpha + psum;
            m_run[r] = m_new;
            const ull a2 = dup2(alpha);
            o2[r][0] = mul2(o2[r][0], a2);
            o2[r][1] = mul2(o2[r][1], a2);
        }

#pragma unroll
        for (int ss = 0; ss < 4; ss++) {
            ull* pr = Pd + (size_t)(j + 16 * ss) * PP + 4 * i;
            pr[0] = dup2(p4[0][ss]); pr[1] = dup2(p4[1][ss]);
            pr[2] = dup2(p4[2][ss]); pr[3] = dup2(p4[3][ss]);
        }
        __syncwarp();

#pragma unroll 4
        for (int k = 0; k < 64; k++) {
            ulonglong2 pa = *(const ulonglong2*)(Pd + (size_t)k * PP + 4 * i);
            ulonglong2 pb = *(const ulonglong2*)(Pd + (size_t)k * PP + 4 * i + 2);
            ulonglong2 vv = *(const ulonglong2*)(Vs + k * PAD + 4 * j);
            fma2(o2[0][0], pa.x, vv.x); fma2(o2[0][1], pa.x, vv.y);
            fma2(o2[1][0], pa.y, vv.x); fma2(o2[1][1], pa.y, vv.y);
            fma2(o2[2][0], pb.x, vv.x); fma2(o2[2][1], pb.x, vv.y);
            fma2(o2[3][0], pb.y, vv.x); fma2(o2[3][1], pb.y, vv.y);
        }
    }

    const int b = bh >> 4, h = bh & 15;
#pragma unroll
    for (int r = 0; r < 4; r++) {
        const float il = 1.0f / l_run[r];
        float2 f0 = unpack2(o2[r][0]);
        float2 f1 = unpack2(o2[r][1]);
        float* dst = Y + ((size_t)b * T_ + qt * 64 + 4 * i + r) * C_ + h * D_ + 4 * j;
        *(float4*)dst = make_float4(f0.x * il, f0.y * il, f1.x * il, f1.y * il);
    }
}

// ==========================================================================
extern "C" void kernel_launch(void* const* d_in, const int* in_sizes, int n_in,
                              void* d_out, int out_size)
{
    const float* x   = (const float*)d_in[0];
    const float* Wq  = (const float*)d_in[1];
    const float* Wk  = (const float*)d_in[2];
    const float* Wv  = (const float*)d_in[3];
    const float* Wo  = (const float*)d_in[4];
    const float* sqk = (const float*)d_in[5];
    float* out = (float*)d_out;

    static float *q = nullptr, *k, *v, *qn, *kn, *vn, *att;
    static __nv_bfloat16 *xs, *ws, *as;
    static bool init_done = false;
    const size_t attn_smem = (size_t)3 * 64 * PAD * sizeof(float) + (size_t)64 * PP * 8;
    if (!init_done) {
        cudaGetSymbolAddress((void**)&q,   g_q);
        cudaGetSymbolAddress((void**)&k,   g_k);
        cudaGetSymbolAddress((void**)&v,   g_v);
        cudaGetSymbolAddress((void**)&qn,  g_qn);
        cudaGetSymbolAddress((void**)&kn,  g_kn);
        cudaGetSymbolAddress((void**)&vn,  g_vn);
        cudaGetSymbolAddress((void**)&att, g_att);
        cudaGetSymbolAddress((void**)&xs,  g_xs);
        cudaGetSymbolAddress((void**)&ws,  g_ws);
        cudaGetSymbolAddress((void**)&as,  g_as);
        cudaFuncSetAttribute(attn_kernel,
                             cudaFuncAttributeMaxDynamicSharedMemorySize, (int)attn_smem);
        cudaFuncSetAttribute(gemm_hmma_kernel,
                             cudaFuncAttributeMaxDynamicSharedMemorySize, GSMEM);
        init_done = true;
    }

    // split x and the 4 weight matrices to bf16 hi/lo planes
    split_kernel<<<AELEM / 4 / 256, 256>>>((const float4*)x, (uint2*)xs,
                                           (uint2*)(xs + AELEM));
    split_w_kernel<<<dim3(WELEM / 4 / 256, 1, 4), 256>>>(Wq, Wk, Wv, Wo, ws);

    // QKV projections on HMMA (bf16x3)
    gemm_hmma_kernel<<<dim3(8, 32, 3), 256, GSMEM>>>(xs, ws, q, k, v);

    rope_norm_kernel<<<(BT_ * H_) / 8, 256>>>(q, k, v, sqk, qn, kn, vn);

    attn_kernel<<<dim3(T_ / 64, BH_), 256, attn_smem>>>(qn, kn, vn, att);

    // split attention output, then Wo projection on HMMA
    split_kernel<<<AELEM / 4 / 256, 256>>>((const float4*)att, (uint2*)as,
                                           (uint2*)(as + AELEM));
    gemm_hmma_kernel<<<dim3(8, 32, 1), 256, GSMEM>>>(as, ws + (size_t)3 * 2 * WELEM,
                                                     out, out, out);
}

// round 11
// speedup vs baseline: 2.6542x; 1.2543x over previous
#include <cuda_runtime.h>
#include <cuda_bf16.h>
#include <cstdint>

typedef unsigned long long ull;

constexpr int B_ = 2, T_ = 2048, C_ = 1024, H_ = 16, D_ = 64;
constexpr int BT_ = B_ * T_;   // 4096
constexpr int BH_ = B_ * H_;   // 32
constexpr int AELEM = BT_ * C_;      // 4194304
constexpr int WELEM = C_ * C_;       // 1048576

// ---------------- scratch (static device arrays; no allocation allowed) ----
__device__ float g_q [BT_ * C_];
__device__ float g_k [BT_ * C_];
__device__ float g_v [BT_ * C_];
__device__ float g_qn[BT_ * C_];   // reused: Q bf16 hi plane | lo plane  [BH][T][D]
__device__ float g_kn[BT_ * C_];   // reused: K bf16 hi plane | lo plane  [BH][T][D]
__device__ float g_vn[BT_ * C_];   // V fp32 [BH][T][D]
__device__ float g_att[BT_ * C_];  // [BT][C]

__device__ __nv_bfloat16 g_xs [2 * AELEM];      // x  split: hi | lo
__device__ __nv_bfloat16 g_ws [4 * 2 * WELEM];  // Wq,Wk,Wv,Wo: per-matrix hi | lo
__device__ __nv_bfloat16 g_as [2 * AELEM];      // att split: hi | lo

// ---------------- f32x2 helpers (FFMA2) -----------------------------------
__device__ __forceinline__ void fma2(ull& c, ull a, ull b) {
    asm("fma.rn.f32x2 %0, %1, %2, %3;" : "=l"(c) : "l"(a), "l"(b), "l"(c));
}
__device__ __forceinline__ ull mul2(ull a, ull b) {
    ull r; asm("mul.rn.f32x2 %0, %1, %2;" : "=l"(r) : "l"(a), "l"(b)); return r;
}
__device__ __forceinline__ ull dup2(float x) {
    ull r; asm("mov.b64 %0, {%1, %1};" : "=l"(r) : "f"(x)); return r;
}
__device__ __forceinline__ float2 unpack2(ull v) {
    float lo, hi; asm("mov.b64 {%0, %1}, %2;" : "=f"(lo), "=f"(hi) : "l"(v));
    return make_float2(lo, hi);
}
__device__ __forceinline__ uint32_t smem_u32(const void* p) {
    uint32_t a;
    asm("{ .reg .u64 t; cvta.to.shared.u64 t, %1; cvt.u32.u64 %0, t; }" : "=r"(a) : "l"(p));
    return a;
}

// ==========================================================================
// Split fp32 -> bf16 (hi) + bf16(residual) (lo).  4 elements / thread.
// ==========================================================================
__global__ void __launch_bounds__(256) split_kernel(
    const float4* __restrict__ in, uint2* __restrict__ hi, uint2* __restrict__ lo)
{
    const int i = blockIdx.x * blockDim.x + threadIdx.x;
    float4 f = in[i];
    uint32_t h0, h1;
    asm("cvt.rn.bf16x2.f32 %0, %1, %2;" : "=r"(h0) : "f"(f.y), "f"(f.x));
    asm("cvt.rn.bf16x2.f32 %0, %1, %2;" : "=r"(h1) : "f"(f.w), "f"(f.z));
    float r0 = f.x - __uint_as_float(h0 << 16);
    float r1 = f.y - __uint_as_float(h0 & 0xffff0000u);
    float r2 = f.z - __uint_as_float(h1 << 16);
    float r3 = f.w - __uint_as_float(h1 & 0xffff0000u);
    uint32_t l0, l1;
    asm("cvt.rn.bf16x2.f32 %0, %1, %2;" : "=r"(l0) : "f"(r1), "f"(r0));
    asm("cvt.rn.bf16x2.f32 %0, %1, %2;" : "=r"(l1) : "f"(r3), "f"(r2));
    hi[i] = make_uint2(h0, h1);
    lo[i] = make_uint2(l0, l1);
}

// W splitter: grid.z selects which W; outputs into g_ws + z*2*WELEM.
__global__ void __launch_bounds__(256) split_w_kernel(
    const float* __restrict__ W0, const float* __restrict__ W1,
    const float* __restrict__ W2, const float* __restrict__ W3,
    __nv_bfloat16* __restrict__ ws)
{
    const float* W = (blockIdx.z == 0) ? W0 : (blockIdx.z == 1) ? W1
                   : (blockIdx.z == 2) ? W2 : W3;
    const int i = blockIdx.x * blockDim.x + threadIdx.x;
    float4 f = ((const float4*)W)[i];
    uint32_t h0, h1;
    asm("cvt.rn.bf16x2.f32 %0, %1, %2;" : "=r"(h0) : "f"(f.y), "f"(f.x));
    asm("cvt.rn.bf16x2.f32 %0, %1, %2;" : "=r"(h1) : "f"(f.w), "f"(f.z));
    float r0 = f.x - __uint_as_float(h0 << 16);
    float r1 = f.y - __uint_as_float(h0 & 0xffff0000u);
    float r2 = f.z - __uint_as_float(h1 << 16);
    float r3 = f.w - __uint_as_float(h1 & 0xffff0000u);
    uint32_t l0, l1;
    asm("cvt.rn.bf16x2.f32 %0, %1, %2;" : "=r"(l0) : "f"(r1), "f"(r0));
    asm("cvt.rn.bf16x2.f32 %0, %1, %2;" : "=r"(l1) : "f"(r3), "f"(r2));
    uint2* hi = (uint2*)(ws + (size_t)blockIdx.z * 2 * WELEM);
    uint2* lo = (uint2*)(ws + (size_t)blockIdx.z * 2 * WELEM + WELEM);
    hi[i] = make_uint2(h0, h1);
    lo[i] = make_uint2(l0, l1);
}

// ==========================================================================
// HMMA building blocks (validated in R10)
// ==========================================================================
#define CPA16(dst, src) \
    asm volatile("cp.async.cg.shared.global [%0], [%1], 16;" :: "r"(dst), "l"(src))
#define CPA_COMMIT() asm volatile("cp.async.commit_group;" ::: "memory")

#define LDM_X4(r0, r1, r2, r3, a) \
    asm volatile("ldmatrix.sync.aligned.m8n8.x4.shared.b16 {%0,%1,%2,%3}, [%4];" \
                 : "=r"(r0), "=r"(r1), "=r"(r2), "=r"(r3) : "r"(a))

#define MMA16816(c, a, b) \
    asm volatile("mma.sync.aligned.m16n8k16.row.col.f32.bf16.bf16.f32 " \
                 "{%0,%1,%2,%3}, {%4,%5,%6,%7}, {%8,%9}, {%0,%1,%2,%3};" \
                 : "+f"((c)[0]), "+f"((c)[1]), "+f"((c)[2]), "+f"((c)[3]) \
                 : "r"((a)[0]), "r"((a)[1]), "r"((a)[2]), "r"((a)[3]), \
                   "r"((b)[0]), "r"((b)[1]))

// ==========================================================================
// HMMA GEMM (unchanged from R10): O[m,n] = sum_k A[m,k] * W[n,k], bf16x3.
// ==========================================================================
constexpr int GST   = 40;                    // smem row stride (bf16)
constexpr int PLANE = 128 * GST * 2;         // 10240 B
constexpr int GBUF  = 4 * PLANE;             // 40960 B
constexpr int GSMEM = 2 * GBUF;              // 81920 B

__global__ void __launch_bounds__(256) gemm_hmma_kernel(
    const __nv_bfloat16* __restrict__ As,
    const __nv_bfloat16* __restrict__ Ws,
    float* __restrict__ O0, float* __restrict__ O1, float* __restrict__ O2)
{
    extern __shared__ char smem[];
    const uint32_t sb = smem_u32(smem);
    const int tid  = threadIdx.x;
    const int wid  = tid >> 5, lane = tid & 31;
    const int m0   = blockIdx.y * 128;
    const int n0   = blockIdx.x * 128;
    const int wm   = (wid & 1) * 64;
    const int wn   = (wid >> 1) * 32;

    float* O = (blockIdx.z == 0) ? O0 : ((blockIdx.z == 1) ? O1 : O2);
    const __nv_bfloat16* Ah = As;
    const __nv_bfloat16* Al = As + AELEM;
    const __nv_bfloat16* Bh = Ws + (size_t)blockIdx.z * 2 * WELEM;
    const __nv_bfloat16* Bl = Bh + WELEM;

    const int lrow = tid >> 2;
    const int lk8  = (tid & 3) * 8;

    float acc[4][4][4];
#pragma unroll
    for (int i = 0; i < 4; i++)
#pragma unroll
        for (int j = 0; j < 4; j++)
#pragma unroll
            for (int c = 0; c < 4; c++) acc[i][j][c] = 0.0f;

    const uint32_t aBase = (uint32_t)((wm + (lane & 15)) * (GST * 2) + (lane >> 4) * 16);
    const uint32_t bBase = (uint32_t)((wn + (lane & 7) + ((lane >> 4) & 1) * 8) * (GST * 2)
                                      + ((lane >> 3) & 1) * 16);

    auto issue_stage = [&](int kt, int buf) {
        const int k0 = kt * 32;
        const uint32_t dbase = sb + buf * GBUF;
#pragma unroll
        for (int h = 0; h < 2; h++) {
            const int row = lrow + h * 64;
            const uint32_t doff = (uint32_t)(row * (GST * 2) + lk8 * 2);
            CPA16(dbase + 0 * PLANE + doff, Ah + (size_t)(m0 + row) * 1024 + k0 + lk8);
            CPA16(dbase + 1 * PLANE + doff, Al + (size_t)(m0 + row) * 1024 + k0 + lk8);
            CPA16(dbase + 2 * PLANE + doff, Bh + (size_t)(n0 + row) * 1024 + k0 + lk8);
            CPA16(dbase + 3 * PLANE + doff, Bl + (size_t)(n0 + row) * 1024 + k0 + lk8);
        }
        CPA_COMMIT();
    };

    issue_stage(0, 0);

    for (int kt = 0; kt < 32; ++kt) {
        const int buf = kt & 1;
        if (kt + 1 < 32) {
            issue_stage(kt + 1, (kt + 1) & 1);
            asm volatile("cp.async.wait_group 1;" ::: "memory");
        } else {
            asm volatile("cp.async.wait_group 0;" ::: "memory");
        }
        __syncthreads();

        const uint32_t bbase = sb + buf * GBUF;
#pragma unroll
        for (int k16 = 0; k16 < 2; ++k16) {
            const uint32_t ko = (uint32_t)(k16 * 32);
            uint32_t ah[4][4], al[4][4];
#pragma unroll
            for (int i = 0; i < 4; i++) {
                LDM_X4(ah[i][0], ah[i][1], ah[i][2], ah[i][3],
                       bbase + 0 * PLANE + aBase + i * (16 * GST * 2) + ko);
                LDM_X4(al[i][0], al[i][1], al[i][2], al[i][3],
                       bbase + 1 * PLANE + aBase + i * (16 * GST * 2) + ko);
            }
            uint32_t bh[4][2], bl[4][2];
#pragma unroll
            for (int j2 = 0; j2 < 2; j2++) {
                uint32_t r0, r1, r2, r3;
                LDM_X4(r0, r1, r2, r3,
                       bbase + 2 * PLANE + bBase + j2 * (16 * GST * 2) + ko);
                bh[2 * j2][0] = r0; bh[2 * j2][1] = r1;
                bh[2 * j2 + 1][0] = r2; bh[2 * j2 + 1][1] = r3;
                LDM_X4(r0, r1, r2, r3,
                       bbase + 3 * PLANE + bBase + j2 * (16 * GST * 2) + ko);
                bl[2 * j2][0] = r0; bl[2 * j2][1] = r1;
                bl[2 * j2 + 1][0] = r2; bl[2 * j2 + 1][1] = r3;
            }
#pragma unroll
            for (int i = 0; i < 4; i++)
#pragma unroll
                for (int j = 0; j < 4; j++) {
                    MMA16816(acc[i][j], ah[i], bh[j]);
                    MMA16816(acc[i][j], ah[i], bl[j]);
                    MMA16816(acc[i][j], al[i], bh[j]);
                }
        }
        __syncthreads();
    }

    const int r0 = lane >> 2, c0 = (lane & 3) * 2;
#pragma unroll
    for (int i = 0; i < 4; i++) {
#pragma unroll
        for (int j = 0; j < 4; j++) {
            float* p = O + (size_t)(m0 + wm + i * 16 + r0) * 1024 + n0 + wn + j * 8 + c0;
            *(float2*)p = make_float2(acc[i][j][0], acc[i][j][1]);
            *(float2*)(p + 8 * 1024) = make_float2(acc[i][j][2], acc[i][j][3]);
        }
    }
}

// ==========================================================================
// RoPE + L2 norm + scale; emits Q,K as bf16 hi/lo planes and V fp32,
// all in [BH][T][D] layout.
// ==========================================================================
__global__ void __launch_bounds__(256) rope_norm_kernel(
    const float* __restrict__ tq, const float* __restrict__ tk, const float* __restrict__ tv,
    const float* __restrict__ sqk,
    __nv_bfloat16* __restrict__ Qp,   // hi plane; lo at +AELEM
    __nv_bfloat16* __restrict__ Kp,   // hi plane; lo at +AELEM
    float* __restrict__ Vn)
{
    const int gw   = (blockIdx.x * blockDim.x + threadIdx.x) >> 5;
    const int lane = threadIdx.x & 31;
    const int h  = gw & (H_ - 1);
    const int bt = gw >> 4;
    const int t  = bt & (T_ - 1);
    const int b  = bt >> 11;
    const int p  = lane;

    const size_t src = (size_t)bt * C_ + h * D_ + 2 * p;
    float2 q2 = *(const float2*)(tq + src);
    float2 k2 = *(const float2*)(tk + src);
    float2 v2 = *(const float2*)(tv + src);

    const float ex   = -((float)(2 * p) / (float)D_) * 13.287712379549449f;
    const float invf = exp2f(ex);
    float sn, cs;
    sincosf((float)t * invf, &sn, &cs);

    float2 qr, kr;
    qr.x = q2.x * cs - q2.y * sn;  qr.y = q2.y * cs + q2.x * sn;
    kr.x = k2.x * cs - k2.y * sn;  kr.y = k2.y * cs + k2.x * sn;

    float qs = qr.x * qr.x + qr.y * qr.y;
    float ks = kr.x * kr.x + kr.y * kr.y;
#pragma unroll
    for (int o = 16; o > 0; o >>= 1) {
        qs += __shfl_xor_sync(0xffffffffu, qs, o);
        ks += __shfl_xor_sync(0xffffffffu, ks, o);
    }
    const float qn = fmaxf(sqrtf(qs), 1e-12f);
    const float kn = fmaxf(sqrtf(ks), 1e-12f);

    float2 sc = *(const float2*)(sqk + h * D_ + 2 * p);
    const float iq = (32.0f * 8.0f) / qn;   // s_qk scale 32, sqrt(D)=8 folded in q
    const float ik = 32.0f / kn;

    const float q0 = qr.x * iq * sc.x, q1 = qr.y * iq * sc.y;
    const float k0 = kr.x * ik * sc.x, k1 = kr.y * ik * sc.y;

    uint32_t qhi, khi;
    asm("cvt.rn.bf16x2.f32 %0, %1, %2;" : "=r"(qhi) : "f"(q1), "f"(q0));
    asm("cvt.rn.bf16x2.f32 %0, %1, %2;" : "=r"(khi) : "f"(k1), "f"(k0));
    const float qr0 = q0 - __uint_as_float(qhi << 16);
    const float qr1 = q1 - __uint_as_float(qhi & 0xffff0000u);
    const float kr0 = k0 - __uint_as_float(khi << 16);
    const float kr1 = k1 - __uint_as_float(khi & 0xffff0000u);
    uint32_t qlo, klo;
    asm("cvt.rn.bf16x2.f32 %0, %1, %2;" : "=r"(qlo) : "f"(qr1), "f"(qr0));
    asm("cvt.rn.bf16x2.f32 %0, %1, %2;" : "=r"(klo) : "f"(kr1), "f"(kr0));

    const size_t dst = (((size_t)(b * H_ + h)) * T_ + t) * D_ + 2 * p;
    *(uint32_t*)(Qp + dst)         = qhi;
    *(uint32_t*)(Qp + AELEM + dst) = qlo;
    *(uint32_t*)(Kp + dst)         = khi;
    *(uint32_t*)(Kp + AELEM + dst) = klo;
    *(float2*)(Vn + dst) = v2;
}

// ==========================================================================
// Flash attention v3: S = Q.K^T on HMMA bf16x3 (warps 0-3, m16n64 each,
// Q fragments register-resident), softmax on fragments, P.V on FFMA2
// (all 8 warps, R10 layout).  K(hi/lo)/V double-buffered via cp.async.
// ==========================================================================
constexpr int KSTR  = 144;                 // K/Q smem row stride bytes (72 bf16)
constexpr int KPL   = 64 * KSTR;           // 9216 B per plane
constexpr int VSTRf = 68;                  // V row stride floats
constexpr int VPL   = 64 * VSTRf * 4;      // 17408 B
constexpr int PP    = 66;                  // Pd row pitch (ull)
constexpr int AT_K0 = 0;                   // [buf][hi,lo] : 4*KPL = 36864
constexpr int AT_V0 = 4 * KPL;             // 36864 ; 2*VPL = 34816
constexpr int AT_PD = AT_V0 + 2 * VPL;     // 71680 ; 64*PP*8 = 33792
constexpr int AT_AL = AT_PD + 64 * PP * 8; // 105472 ; 64 ull = 512
constexpr int AT_LI = AT_AL + 512;         // 105984 ; 64 f = 256
constexpr int AT_SM = AT_LI + 256;         // 106240 bytes

__global__ void __launch_bounds__(256, 2) attn_kernel(
    const __nv_bfloat16* __restrict__ Qp,   // hi; lo at +AELEM
    const __nv_bfloat16* __restrict__ Kp,   // hi; lo at +AELEM
    const float* __restrict__ Vn, float* __restrict__ Y)
{
    extern __shared__ char smc[];
    const uint32_t sb = smem_u32(smc);
    ull*   Pd     = (ull*)(smc + AT_PD);
    ull*   alphaD = (ull*)(smc + AT_AL);
    float* linv   = (float*)(smc + AT_LI);
    float* Vs0    = (float*)(smc + AT_V0);

    const int tid = threadIdx.x;
    const int wid = tid >> 5, lane = tid & 31;
    const int i   = tid >> 4;             // PV row group (rows 4i..4i+3)
    const int j   = tid & 15;             // PV d-col group

    const int bh = blockIdx.y;
    const int qt = blockIdx.x;

    const __nv_bfloat16* Qgh = Qp + ((size_t)bh * T_ + qt * 64) * D_;
    const __nv_bfloat16* Qgl = Qgh + AELEM;
    const __nv_bfloat16* Kgh = Kp + (size_t)bh * T_ * D_;
    const __nv_bfloat16* Kgl = Kgh + AELEM;
    const float*         Vg0 = Vn + (size_t)bh * T_ * D_;

    // prefetch issue: K hi/lo (2 chunks each) + V (4 chunks) per thread
    auto issue = [&](int kt) {
        const int b = kt & 1;
        const __nv_bfloat16* kh = Kgh + (size_t)kt * 64 * D_;
        const __nv_bfloat16* kl = Kgl + (size_t)kt * 64 * D_;
        const float*         vg = Vg0 + (size_t)kt * 64 * D_;
        const uint32_t kd = sb + AT_K0 + b * 2 * KPL;
#pragma unroll
        for (int t = 0; t < 2; t++) {
            const int c = tid + t * 256;
            const int row = c >> 3, o = c & 7;
            CPA16(kd + row * KSTR + o * 16,        kh + row * 64 + o * 8);
            CPA16(kd + KPL + row * KSTR + o * 16,  kl + row * 64 + o * 8);
        }
        const uint32_t vd = sb + AT_V0 + b * VPL;
#pragma unroll
        for (int t = 0; t < 4; t++) {
            const int c = tid + t * 256;
            const int row = c >> 4, o = c & 15;
            CPA16(vd + row * (VSTRf * 4) + o * 16, vg + row * 64 + o * 4);
        }
        CPA_COMMIT();
    };

    issue(0);

    // stage Q hi/lo into smem (aliased over Pd region), ldmatrix frags once
    {
        char* qstg = smc + AT_PD;
#pragma unroll
        for (int t = 0; t < 2; t++) {
            const int c = tid + t * 256;
            const int row = c >> 3, o = c & 7;
            *(uint4*)(qstg + row * KSTR + o * 16) =
                *(const uint4*)(Qgh + row * 64 + o * 8);
            *(uint4*)(qstg + KPL + row * KSTR + o * 16) =
                *(const uint4*)(Qgl + row * 64 + o * 8);
        }
    }
    __syncthreads();

    uint32_t qh[4][4], ql[4][4];
    if (wid < 4) {
        const uint32_t aaddr = sb + AT_PD
            + (16 * wid + (lane & 15)) * KSTR + (lane >> 4) * 16;
#pragma unroll
        for (int k16 = 0; k16 < 4; k16++) {
            LDM_X4(qh[k16][0], qh[k16][1], qh[k16][2], qh[k16][3], aaddr + k16 * 32);
            LDM_X4(ql[k16][0], ql[k16][1], ql[k16][2], ql[k16][3],
                   aaddr + KPL + k16 * 32);
        }
    }

    float m0r = -3.0e38f, m1r = -3.0e38f, l0r = 0.0f, l1r = 0.0f;
    ull o2[4][2];
#pragma unroll
    for (int r = 0; r < 4; r++) { o2[r][0] = 0ull; o2[r][1] = 0ull; }

    const uint32_t bBase = ((lane & 7) + ((lane >> 4) & 1) * 8) * KSTR
                         + ((lane >> 3) & 1) * 16;
    const int r0 = 16 * wid + (lane >> 2);      // S row 0 (warps 0-3)
    const int r1 = r0 + 8;                      // S row 1

    for (int kt = 0; kt < T_ / 64; kt++) {
        const int buf = kt & 1;
        asm volatile("cp.async.wait_group 0;" ::: "memory");
        __syncthreads();                         // tile kt ready; PV(kt-1) done
        if (kt + 1 < T_ / 64) issue(kt + 1);     // into the now-free buffer

        if (wid < 4) {
            // ---- S = Q.K^T : m16n64, 3-term bf16 ----
            float sacc[8][4];
#pragma unroll
            for (int n = 0; n < 8; n++)
#pragma unroll
                for (int c = 0; c < 4; c++) sacc[n][c] = 0.0f;

            const uint32_t kbase = sb + AT_K0 + buf * 2 * KPL + bBase;
#pragma unroll
            for (int k16 = 0; k16 < 4; k16++) {
                uint32_t kb[8][2];
#pragma unroll
                for (int nt = 0; nt < 4; nt++) {
                    uint32_t a0, a1, a2, a3;
                    LDM_X4(a0, a1, a2, a3, kbase + nt * (16 * KSTR) + k16 * 32);
                    kb[2 * nt][0] = a0; kb[2 * nt][1] = a1;
                    kb[2 * nt + 1][0] = a2; kb[2 * nt + 1][1] = a3;
                }
#pragma unroll
                for (int n = 0; n < 8; n++) MMA16816(sacc[n], qh[k16], kb[n]);
#pragma unroll
                for (int n = 0; n < 8; n++) MMA16816(sacc[n], ql[k16], kb[n]);
#pragma unroll
                for (int nt = 0; nt < 4; nt++) {
                    uint32_t a0, a1, a2, a3;
                    LDM_X4(a0, a1, a2, a3,
                           kbase + KPL + nt * (16 * KSTR) + k16 * 32);
                    kb[2 * nt][0] = a0; kb[2 * nt][1] = a1;
                    kb[2 * nt + 1][0] = a2; kb[2 * nt + 1][1] = a3;
                }
#pragma unroll
                for (int n = 0; n < 8; n++) MMA16816(sacc[n], qh[k16], kb[n]);
            }

            // ---- softmax on fragments (rows r0, r1) ----
            float mt0 = sacc[0][0], mt1 = sacc[0][2];
#pragma unroll
            for (int n = 0; n < 8; n++) {
                mt0 = fmaxf(mt0, fmaxf(sacc[n][0], sacc[n][1]));
                mt1 = fmaxf(mt1, fmaxf(sacc[n][2], sacc[n][3]));
            }
            mt0 = fmaxf(mt0, __shfl_xor_sync(0xffffffffu, mt0, 1));
            mt0 = fmaxf(mt0, __shfl_xor_sync(0xffffffffu, mt0, 2));
            mt1 = fmaxf(mt1, __shfl_xor_sync(0xffffffffu, mt1, 1));
            mt1 = fmaxf(mt1, __shfl_xor_sync(0xffffffffu, mt1, 2));
            const float mn0 = fmaxf(m0r, mt0), mn1 = fmaxf(m1r, mt1);
            const float al0 = __expf(m0r - mn0), al1 = __expf(m1r - mn1);

            float ps0 = 0.0f, ps1 = 0.0f;
            const int cb = (lane & 3) * 2;
#pragma unroll
            for (int n = 0; n < 8; n++) {
                const int col = n * 8 + cb;
                const float p00 = __expf(sacc[n][0] - mn0);
                const float p01 = __expf(sacc[n][1] - mn0);
                const float p10 = __expf(sacc[n][2] - mn1);
                const float p11 = __expf(sacc[n][3] - mn1);
                ps0 += p00 + p01; ps1 += p10 + p11;
                Pd[(size_t)(col + 0) * PP + r0] = dup2(p00);
                Pd[(size_t)(col + 1) * PP + r0] = dup2(p01);
                Pd[(size_t)(col + 0) * PP + r1] = dup2(p10);
                Pd[(size_t)(col + 1) * PP + r1] = dup2(p11);
            }
            ps0 += __shfl_xor_sync(0xffffffffu, ps0, 1);
            ps0 += __shfl_xor_sync(0xffffffffu, ps0, 2);
            ps1 += __shfl_xor_sync(0xffffffffu, ps1, 1);
            ps1 += __shfl_xor_sync(0xffffffffu, ps1, 2);
            l0r = l0r * al0 + ps0;  m0r = mn0;
            l1r = l1r * al1 + ps1;  m1r = mn1;
            if ((lane & 3) == 0) {
                alphaD[r0] = dup2(al0);
                alphaD[r1] = dup2(al1);
                if (kt == T_ / 64 - 1) {
                    linv[r0] = 1.0f / l0r;
                    linv[r1] = 1.0f / l1r;
                }
            }
        }
        __syncthreads();                         // Pd, alphaD ready

        // ---- rescale + PV (all 8 warps) ----
        {
            ulonglong2 a01 = *(const ulonglong2*)&alphaD[4 * i];
            ulonglong2 a23 = *(const ulonglong2*)&alphaD[4 * i + 2];
            o2[0][0] = mul2(o2[0][0], a01.x); o2[0][1] = mul2(o2[0][1], a01.x);
            o2[1][0] = mul2(o2[1][0], a01.y); o2[1][1] = mul2(o2[1][1], a01.y);
            o2[2][0] = mul2(o2[2][0], a23.x); o2[2][1] = mul2(o2[2][1], a23.x);
            o2[3][0] = mul2(o2[3][0], a23.y); o2[3][1] = mul2(o2[3][1], a23.y);
        }
        const float* Vs = Vs0 + buf * (VPL / 4);
#pragma unroll 4
        for (int k = 0; k < 64; k++) {
            ulonglong2 pa = *(const ulonglong2*)(Pd + (size_t)k * PP + 4 * i);
            ulonglong2 pb = *(const ulonglong2*)(Pd + (size_t)k * PP + 4 * i + 2);
            ulonglong2 vv = *(const ulonglong2*)(Vs + k * VSTRf + 4 * j);
            fma2(o2[0][0], pa.x, vv.x); fma2(o2[0][1], pa.x, vv.y);
            fma2(o2[1][0], pa.y, vv.x); fma2(o2[1][1], pa.y, vv.y);
            fma2(o2[2][0], pb.x, vv.x); fma2(o2[2][1], pb.x, vv.y);
            fma2(o2[3][0], pb.y, vv.x); fma2(o2[3][1], pb.y, vv.y);
        }
    }

    // ---- epilogue: O * linv, write [BT][C] for the Wo GEMM ----
    const int b = bh >> 4, h = bh & 15;
    float4 li = *(const float4*)&linv[4 * i];
    const float lis[4] = { li.x, li.y, li.z, li.w };
#pragma unroll
    for (int r = 0; r < 4; r++) {
        float2 f0 = unpack2(o2[r][0]);
        float2 f1 = unpack2(o2[r][1]);
        float* dst = Y + ((size_t)b * T_ + qt * 64 + 4 * i + r) * C_ + h * D_ + 4 * j;
        *(float4*)dst = make_float4(f0.x * lis[r], f0.y * lis[r],
                                    f1.x * lis[r], f1.y * lis[r]);
    }
}

// ==========================================================================
extern "C" void kernel_launch(void* const* d_in, const int* in_sizes, int n_in,
                              void* d_out, int out_size)
{
    const float* x   = (const float*)d_in[0];
    const float* Wq  = (const float*)d_in[1];
    const float* Wk  = (const float*)d_in[2];
    const float* Wv  = (const float*)d_in[3];
    const float* Wo  = (const float*)d_in[4];
    const float* sqk = (const float*)d_in[5];
    float* out = (float*)d_out;

    static float *q = nullptr, *k, *v, *qn, *kn, *vn, *att;
    static __nv_bfloat16 *xs, *ws, *as;
    static bool init_done = false;
    if (!init_done) {
        cudaGetSymbolAddress((void**)&q,   g_q);
        cudaGetSymbolAddress((void**)&k,   g_k);
        cudaGetSymbolAddress((void**)&v,   g_v);
        cudaGetSymbolAddress((void**)&qn,  g_qn);
        cudaGetSymbolAddress((void**)&kn,  g_kn);
        cudaGetSymbolAddress((void**)&vn,  g_vn);
        cudaGetSymbolAddress((void**)&att, g_att);
        cudaGetSymbolAddress((void**)&xs,  g_xs);
        cudaGetSymbolAddress((void**)&ws,  g_ws);
        cudaGetSymbolAddress((void**)&as,  g_as);
        cudaFuncSetAttribute(attn_kernel,
                             cudaFuncAttributeMaxDynamicSharedMemorySize, AT_SM);
        cudaFuncSetAttribute(gemm_hmma_kernel,
                             cudaFuncAttributeMaxDynamicSharedMemorySize, GSMEM);
        init_done = true;
    }

    // split x and the 4 weight matrices to bf16 hi/lo planes
    split_kernel<<<AELEM / 4 / 256, 256>>>((const float4*)x, (uint2*)xs,
                                           (uint2*)(xs + AELEM));
    split_w_kernel<<<dim3(WELEM / 4 / 256, 1, 4), 256>>>(Wq, Wk, Wv, Wo, ws);

    // QKV projections on HMMA (bf16x3)
    gemm_hmma_kernel<<<dim3(8, 32, 3), 256, GSMEM>>>(xs, ws, q, k, v);

    // RoPE + norm; Q/K emitted as bf16 hi/lo planes, V fp32
    rope_norm_kernel<<<(BT_ * H_) / 8, 256>>>(
        q, k, v, sqk, (__nv_bfloat16*)qn, (__nv_bfloat16*)kn, vn);

    // Flash attention (S on HMMA, PV on FFMA2)
    attn_kernel<<<dim3(T_ / 64, BH_), 256, AT_SM>>>(
        (const __nv_bfloat16*)qn, (const __nv_bfloat16*)kn, vn, att);

    // split attention output, then Wo projection on HMMA
    split_kernel<<<AELEM / 4 / 256, 256>>>((const float4*)att, (uint2*)as,
                                           (uint2*)(as + AELEM));
    gemm_hmma_kernel<<<dim3(8, 32, 1), 256, GSMEM>>>(as, ws + (size_t)3 * 2 * WELEM,
                                                     out, out, out);
}

// round 13
// speedup vs baseline: 4.0348x; 1.5202x over previous
#include <cuda_runtime.h>
#include <cuda_bf16.h>
#include <cstdint>

typedef unsigned long long ull;

constexpr int B_ = 2, T_ = 2048, C_ = 1024, H_ = 16, D_ = 64;
constexpr int BT_ = B_ * T_;   // 4096
constexpr int BH_ = B_ * H_;   // 32
constexpr int AELEM = BT_ * C_;      // 4194304
constexpr int WELEM = C_ * C_;       // 1048576

// ---------------- scratch (static device arrays; no allocation allowed) ----
__device__ float g_q [BT_ * C_];
__device__ float g_k [BT_ * C_];
__device__ float g_v [BT_ * C_];
__device__ float g_qn[BT_ * C_];   // reused: Q bf16 hi|lo planes [BH][T][D]
__device__ float g_kn[BT_ * C_];   // reused: K bf16 hi|lo planes [BH][T][D]
__device__ float g_vn[BT_ * C_];   // reused: V bf16 hi|lo planes [BH][T][D]
__device__ float g_att[BT_ * C_];  // [BT][C]

__device__ __nv_bfloat16 g_xs [2 * AELEM];      // x  split: hi | lo
__device__ __nv_bfloat16 g_ws [4 * 2 * WELEM];  // Wq,Wk,Wv,Wo: per-matrix hi | lo
__device__ __nv_bfloat16 g_as [2 * AELEM];      // att split: hi | lo

// ---------------- helpers --------------------------------------------------
__device__ __forceinline__ uint32_t smem_u32(const void* p) {
    uint32_t a;
    asm("{ .reg .u64 t; cvta.to.shared.u64 t, %1; cvt.u32.u64 %0, t; }" : "=r"(a) : "l"(p));
    return a;
}

// ==========================================================================
// Split fp32 -> bf16 (hi) + bf16(residual) (lo).  4 elements / thread.
// ==========================================================================
__global__ void __launch_bounds__(256) split_kernel(
    const float4* __restrict__ in, uint2* __restrict__ hi, uint2* __restrict__ lo)
{
    const int i = blockIdx.x * blockDim.x + threadIdx.x;
    float4 f = in[i];
    uint32_t h0, h1;
    asm("cvt.rn.bf16x2.f32 %0, %1, %2;" : "=r"(h0) : "f"(f.y), "f"(f.x));
    asm("cvt.rn.bf16x2.f32 %0, %1, %2;" : "=r"(h1) : "f"(f.w), "f"(f.z));
    float r0 = f.x - __uint_as_float(h0 << 16);
    float r1 = f.y - __uint_as_float(h0 & 0xffff0000u);
    float r2 = f.z - __uint_as_float(h1 << 16);
    float r3 = f.w - __uint_as_float(h1 & 0xffff0000u);
    uint32_t l0, l1;
    asm("cvt.rn.bf16x2.f32 %0, %1, %2;" : "=r"(l0) : "f"(r1), "f"(r0));
    asm("cvt.rn.bf16x2.f32 %0, %1, %2;" : "=r"(l1) : "f"(r3), "f"(r2));
    hi[i] = make_uint2(h0, h1);
    lo[i] = make_uint2(l0, l1);
}

// W splitter: grid.z selects which W; outputs into g_ws + z*2*WELEM.
__global__ void __launch_bounds__(256) split_w_kernel(
    const float* __restrict__ W0, const float* __restrict__ W1,
    const float* __restrict__ W2, const float* __restrict__ W3,
    __nv_bfloat16* __restrict__ ws)
{
    const float* W = (blockIdx.z == 0) ? W0 : (blockIdx.z == 1) ? W1
                   : (blockIdx.z == 2) ? W2 : W3;
    const int i = blockIdx.x * blockDim.x + threadIdx.x;
    float4 f = ((const float4*)W)[i];
    uint32_t h0, h1;
    asm("cvt.rn.bf16x2.f32 %0, %1, %2;" : "=r"(h0) : "f"(f.y), "f"(f.x));
    asm("cvt.rn.bf16x2.f32 %0, %1, %2;" : "=r"(h1) : "f"(f.w), "f"(f.z));
    float r0 = f.x - __uint_as_float(h0 << 16);
    float r1 = f.y - __uint_as_float(h0 & 0xffff0000u);
    float r2 = f.z - __uint_as_float(h1 << 16);
    float r3 = f.w - __uint_as_float(h1 & 0xffff0000u);
    uint32_t l0, l1;
    asm("cvt.rn.bf16x2.f32 %0, %1, %2;" : "=r"(l0) : "f"(r1), "f"(r0));
    asm("cvt.rn.bf16x2.f32 %0, %1, %2;" : "=r"(l1) : "f"(r3), "f"(r2));
    uint2* hi = (uint2*)(ws + (size_t)blockIdx.z * 2 * WELEM);
    uint2* lo = (uint2*)(ws + (size_t)blockIdx.z * 2 * WELEM + WELEM);
    hi[i] = make_uint2(h0, h1);
    lo[i] = make_uint2(l0, l1);
}

// ==========================================================================
// HMMA building blocks (validated in R10/R11)
// ==========================================================================
#define CPA16(dst, src) \
    asm volatile("cp.async.cg.shared.global [%0], [%1], 16;" :: "r"(dst), "l"(src))
#define CPA_COMMIT() asm volatile("cp.async.commit_group;" ::: "memory")

#define LDM_X4(r0, r1, r2, r3, a) \
    asm volatile("ldmatrix.sync.aligned.m8n8.x4.shared.b16 {%0,%1,%2,%3}, [%4];" \
                 : "=r"(r0), "=r"(r1), "=r"(r2), "=r"(r3) : "r"(a))

#define LDM_X4_T(r0, r1, r2, r3, a) \
    asm volatile("ldmatrix.sync.aligned.m8n8.x4.trans.shared.b16 {%0,%1,%2,%3}, [%4];" \
                 : "=r"(r0), "=r"(r1), "=r"(r2), "=r"(r3) : "r"(a))

#define MMA16816(c, a, b) \
    asm volatile("mma.sync.aligned.m16n8k16.row.col.f32.bf16.bf16.f32 " \
                 "{%0,%1,%2,%3}, {%4,%5,%6,%7}, {%8,%9}, {%0,%1,%2,%3};" \
                 : "+f"((c)[0]), "+f"((c)[1]), "+f"((c)[2]), "+f"((c)[3]) \
                 : "r"((a)[0]), "r"((a)[1]), "r"((a)[2]), "r"((a)[3]), \
                   "r"((b)[0]), "r"((b)[1]))

// ==========================================================================
// HMMA GEMM (unchanged from R10): O[m,n] = sum_k A[m,k] * W[n,k], bf16x3.
// ==========================================================================
constexpr int GST   = 40;                    // smem row stride (bf16)
constexpr int PLANE = 128 * GST * 2;         // 10240 B
constexpr int GBUF  = 4 * PLANE;             // 40960 B
constexpr int GSMEM = 2 * GBUF;              // 81920 B

__global__ void __launch_bounds__(256) gemm_hmma_kernel(
    const __nv_bfloat16* __restrict__ As,
    const __nv_bfloat16* __restrict__ Ws,
    float* __restrict__ O0, float* __restrict__ O1, float* __restrict__ O2)
{
    extern __shared__ char smem[];
    const uint32_t sb = smem_u32(smem);
    const int tid  = threadIdx.x;
    const int wid  = tid >> 5, lane = tid & 31;
    const int m0   = blockIdx.y * 128;
    const int n0   = blockIdx.x * 128;
    const int wm   = (wid & 1) * 64;
    const int wn   = (wid >> 1) * 32;

    float* O = (blockIdx.z == 0) ? O0 : ((blockIdx.z == 1) ? O1 : O2);
    const __nv_bfloat16* Ah = As;
    const __nv_bfloat16* Al = As + AELEM;
    const __nv_bfloat16* Bh = Ws + (size_t)blockIdx.z * 2 * WELEM;
    const __nv_bfloat16* Bl = Bh + WELEM;

    const int lrow = tid >> 2;
    const int lk8  = (tid & 3) * 8;

    float acc[4][4][4];
#pragma unroll
    for (int i = 0; i < 4; i++)
#pragma unroll
        for (int j = 0; j < 4; j++)
#pragma unroll
            for (int c = 0; c < 4; c++) acc[i][j][c] = 0.0f;

    const uint32_t aBase = (uint32_t)((wm + (lane & 15)) * (GST * 2) + (lane >> 4) * 16);
    const uint32_t bBase = (uint32_t)((wn + (lane & 7) + ((lane >> 4) & 1) * 8) * (GST * 2)
                                      + ((lane >> 3) & 1) * 16);

    auto issue_stage = [&](int kt, int buf) {
        const int k0 = kt * 32;
        const uint32_t dbase = sb + buf * GBUF;
#pragma unroll
        for (int h = 0; h < 2; h++) {
            const int row = lrow + h * 64;
            const uint32_t doff = (uint32_t)(row * (GST * 2) + lk8 * 2);
            CPA16(dbase + 0 * PLANE + doff, Ah + (size_t)(m0 + row) * 1024 + k0 + lk8);
            CPA16(dbase + 1 * PLANE + doff, Al + (size_t)(m0 + row) * 1024 + k0 + lk8);
            CPA16(dbase + 2 * PLANE + doff, Bh + (size_t)(n0 + row) * 1024 + k0 + lk8);
            CPA16(dbase + 3 * PLANE + doff, Bl + (size_t)(n0 + row) * 1024 + k0 + lk8);
        }
        CPA_COMMIT();
    };

    issue_stage(0, 0);

    for (int kt = 0; kt < 32; ++kt) {
        const int buf = kt & 1;
        if (kt + 1 < 32) {
            issue_stage(kt + 1, (kt + 1) & 1);
            asm volatile("cp.async.wait_group 1;" ::: "memory");
        } else {
            asm volatile("cp.async.wait_group 0;" ::: "memory");
        }
        __syncthreads();

        const uint32_t bbase = sb + buf * GBUF;
#pragma unroll
        for (int k16 = 0; k16 < 2; ++k16) {
            const uint32_t ko = (uint32_t)(k16 * 32);
            uint32_t ah[4][4], al[4][4];
#pragma unroll
            for (int i = 0; i < 4; i++) {
                LDM_X4(ah[i][0], ah[i][1], ah[i][2], ah[i][3],
                       bbase + 0 * PLANE + aBase + i * (16 * GST * 2) + ko);
                LDM_X4(al[i][0], al[i][1], al[i][2], al[i][3],
                       bbase + 1 * PLANE + aBase + i * (16 * GST * 2) + ko);
            }
            uint32_t bh[4][2], bl[4][2];
#pragma unroll
            for (int j2 = 0; j2 < 2; j2++) {
                uint32_t r0, r1, r2, r3;
                LDM_X4(r0, r1, r2, r3,
                       bbase + 2 * PLANE + bBase + j2 * (16 * GST * 2) + ko);
                bh[2 * j2][0] = r0; bh[2 * j2][1] = r1;
                bh[2 * j2 + 1][0] = r2; bh[2 * j2 + 1][1] = r3;
                LDM_X4(r0, r1, r2, r3,
                       bbase + 3 * PLANE + bBase + j2 * (16 * GST * 2) + ko);
                bl[2 * j2][0] = r0; bl[2 * j2][1] = r1;
                bl[2 * j2 + 1][0] = r2; bl[2 * j2 + 1][1] = r3;
            }
#pragma unroll
            for (int i = 0; i < 4; i++)
#pragma unroll
                for (int j = 0; j < 4; j++) {
                    MMA16816(acc[i][j], ah[i], bh[j]);
                    MMA16816(acc[i][j], ah[i], bl[j]);
                    MMA16816(acc[i][j], al[i], bh[j]);
                }
        }
        __syncthreads();
    }

    const int r0 = lane >> 2, c0 = (lane & 3) * 2;
#pragma unroll
    for (int i = 0; i < 4; i++) {
#pragma unroll
        for (int j = 0; j < 4; j++) {
            float* p = O + (size_t)(m0 + wm + i * 16 + r0) * 1024 + n0 + wn + j * 8 + c0;
            *(float2*)p = make_float2(acc[i][j][0], acc[i][j][1]);
            *(float2*)(p + 8 * 1024) = make_float2(acc[i][j][2], acc[i][j][3]);
        }
    }
}

// ==========================================================================
// RoPE + L2 norm + scale; emits Q, K, V all as bf16 hi/lo planes [BH][T][D].
// ==========================================================================
__global__ void __launch_bounds__(256) rope_norm_kernel(
    const float* __restrict__ tq, const float* __restrict__ tk, const float* __restrict__ tv,
    const float* __restrict__ sqk,
    __nv_bfloat16* __restrict__ Qp,   // hi plane; lo at +AELEM
    __nv_bfloat16* __restrict__ Kp,
    __nv_bfloat16* __restrict__ Vp)
{
    const int gw   = (blockIdx.x * blockDim.x + threadIdx.x) >> 5;
    const int lane = threadIdx.x & 31;
    const int h  = gw & (H_ - 1);
    const int bt = gw >> 4;
    const int t  = bt & (T_ - 1);
    const int b  = bt >> 11;
    const int p  = lane;

    const size_t src = (size_t)bt * C_ + h * D_ + 2 * p;
    float2 q2 = *(const float2*)(tq + src);
    float2 k2 = *(const float2*)(tk + src);
    float2 v2 = *(const float2*)(tv + src);

    const float ex   = -((float)(2 * p) / (float)D_) * 13.287712379549449f;
    const float invf = exp2f(ex);
    float sn, cs;
    sincosf((float)t * invf, &sn, &cs);

    float2 qr, kr;
    qr.x = q2.x * cs - q2.y * sn;  qr.y = q2.y * cs + q2.x * sn;
    kr.x = k2.x * cs - k2.y * sn;  kr.y = k2.y * cs + k2.x * sn;

    float qs = qr.x * qr.x + qr.y * qr.y;
    float ks = kr.x * kr.x + kr.y * kr.y;
#pragma unroll
    for (int o = 16; o > 0; o >>= 1) {
        qs += __shfl_xor_sync(0xffffffffu, qs, o);
        ks += __shfl_xor_sync(0xffffffffu, ks, o);
    }
    const float qn = fmaxf(sqrtf(qs), 1e-12f);
    const float kn = fmaxf(sqrtf(ks), 1e-12f);

    float2 sc = *(const float2*)(sqk + h * D_ + 2 * p);
    const float iq = (32.0f * 8.0f) / qn;   // s_qk scale 32, sqrt(D)=8 folded in q
    const float ik = 32.0f / kn;

    const float q0 = qr.x * iq * sc.x, q1 = qr.y * iq * sc.y;
    const float k0 = kr.x * ik * sc.x, k1 = kr.y * ik * sc.y;
    const float v0 = v2.x,             v1 = v2.y;

    uint32_t qhi, khi, vhi;
    asm("cvt.rn.bf16x2.f32 %0, %1, %2;" : "=r"(qhi) : "f"(q1), "f"(q0));
    asm("cvt.rn.bf16x2.f32 %0, %1, %2;" : "=r"(khi) : "f"(k1), "f"(k0));
    asm("cvt.rn.bf16x2.f32 %0, %1, %2;" : "=r"(vhi) : "f"(v1), "f"(v0));
    const float qr0 = q0 - __uint_as_float(qhi << 16);
    const float qr1 = q1 - __uint_as_float(qhi & 0xffff0000u);
    const float kr0 = k0 - __uint_as_float(khi << 16);
    const float kr1 = k1 - __uint_as_float(khi & 0xffff0000u);
    const float vr0 = v0 - __uint_as_float(vhi << 16);
    const float vr1 = v1 - __uint_as_float(vhi & 0xffff0000u);
    uint32_t qlo, klo, vlo;
    asm("cvt.rn.bf16x2.f32 %0, %1, %2;" : "=r"(qlo) : "f"(qr1), "f"(qr0));
    asm("cvt.rn.bf16x2.f32 %0, %1, %2;" : "=r"(klo) : "f"(kr1), "f"(kr0));
    asm("cvt.rn.bf16x2.f32 %0, %1, %2;" : "=r"(vlo) : "f"(vr1), "f"(vr0));

    const size_t dst = (((size_t)(b * H_ + h)) * T_ + t) * D_ + 2 * p;
    *(uint32_t*)(Qp + dst)         = qhi;
    *(uint32_t*)(Qp + AELEM + dst) = qlo;
    *(uint32_t*)(Kp + dst)         = khi;
    *(uint32_t*)(Kp + AELEM + dst) = klo;
    *(uint32_t*)(Vp + dst)         = vhi;
    *(uint32_t*)(Vp + AELEM + dst) = vlo;
}

// ==========================================================================
// Flash attention v4: fully tensorized.
//  warps 0-3: S = Q.K^T (HMMA bf16x3, Q frags register-resident) + softmax,
//             P emitted as bf16 hi/lo planes.
//  warps 4-7: O += P.V (HMMA bf16x3, V B-frags via ldmatrix.trans).
//  K/V hi/lo double-buffered via cp.async.
// ==========================================================================
constexpr int KSTR  = 144;                 // smem row stride bytes (72 bf16)
constexpr int KPL   = 64 * KSTR;           // 9216 B per plane
constexpr int AT_K0 = 0;                   // K: 2 buf x 2 planes = 36864
constexpr int AT_V0 = 4 * KPL;             // V: 2 buf x 2 planes = 36864
constexpr int AT_P0 = 8 * KPL;             // P: 2 planes = 18432 (Q staged here)
constexpr int AT_AL = 10 * KPL;            // alphaF: 64 f = 256
constexpr int AT_LI = AT_AL + 256;         // linv: 64 f = 256
constexpr int AT_SM = AT_LI + 256;         // 92672 bytes

__global__ void __launch_bounds__(256, 2) attn_kernel(
    const __nv_bfloat16* __restrict__ Qp,   // hi; lo at +AELEM
    const __nv_bfloat16* __restrict__ Kp,
    const __nv_bfloat16* __restrict__ Vp,
    float* __restrict__ Y)
{
    extern __shared__ char smc[];
    const uint32_t sb = smem_u32(smc);
    float* alphaF = (float*)(smc + AT_AL);
    float* linv   = (float*)(smc + AT_LI);

    const int tid = threadIdx.x;
    const int wid = tid >> 5, lane = tid & 31;

    const int bh = blockIdx.y;
    const int qt = blockIdx.x;

    const __nv_bfloat16* Qgh = Qp + ((size_t)bh * T_ + qt * 64) * D_;
    const __nv_bfloat16* Qgl = Qgh + AELEM;
    const __nv_bfloat16* Kgh = Kp + (size_t)bh * T_ * D_;
    const __nv_bfloat16* Kgl = Kgh + AELEM;
    const __nv_bfloat16* Vgh = Vp + (size_t)bh * T_ * D_;
    const __nv_bfloat16* Vgl = Vgh + AELEM;

    // prefetch: K hi/lo + V hi/lo, 2 chunks per plane per thread
    auto issue = [&](int kt) {
        const int bsel = kt & 1;
        const __nv_bfloat16* kh = Kgh + (size_t)kt * 64 * D_;
        const __nv_bfloat16* kl = Kgl + (size_t)kt * 64 * D_;
        const __nv_bfloat16* vh = Vgh + (size_t)kt * 64 * D_;
        const __nv_bfloat16* vl = Vgl + (size_t)kt * 64 * D_;
        const uint32_t kd = sb + AT_K0 + bsel * 2 * KPL;
        const uint32_t vd = sb + AT_V0 + bsel * 2 * KPL;
#pragma unroll
        for (int t = 0; t < 2; t++) {
            const int c = tid + t * 256;
            const int row = c >> 3, o = c & 7;
            const uint32_t off = row * KSTR + o * 16;
            CPA16(kd + off,       kh + row * 64 + o * 8);
            CPA16(kd + KPL + off, kl + row * 64 + o * 8);
            CPA16(vd + off,       vh + row * 64 + o * 8);
            CPA16(vd + KPL + off, vl + row * 64 + o * 8);
        }
        CPA_COMMIT();
    };

    issue(0);

    // stage Q hi/lo into smem (aliased over P region), load frags once
    {
        char* qstg = smc + AT_P0;
#pragma unroll
        for (int t = 0; t < 2; t++) {
            const int c = tid + t * 256;
            const int row = c >> 3, o = c & 7;
            *(uint4*)(qstg + row * KSTR + o * 16) =
                *(const uint4*)(Qgh + row * 64 + o * 8);
            *(uint4*)(qstg + KPL + row * KSTR + o * 16) =
                *(const uint4*)(Qgl + row * 64 + o * 8);
        }
    }
    __syncthreads();

    uint32_t qh[4][4], ql[4][4];
    if (wid < 4) {
        const uint32_t aaddr = sb + AT_P0
            + (16 * wid + (lane & 15)) * KSTR + (lane >> 4) * 16;
#pragma unroll
        for (int k16 = 0; k16 < 4; k16++) {
            LDM_X4(qh[k16][0], qh[k16][1], qh[k16][2], qh[k16][3], aaddr + k16 * 32);
            LDM_X4(ql[k16][0], ql[k16][1], ql[k16][2], ql[k16][3],
                   aaddr + KPL + k16 * 32);
        }
    }

    // S-warp softmax state
    float m0r = -3.0e38f, m1r = -3.0e38f, l0r = 0.0f, l1r = 0.0f;
    // PV-warp accumulators: m16 x d64 -> 8 n-frags x 4 f32
    float acc[8][4];
#pragma unroll
    for (int n = 0; n < 8; n++)
#pragma unroll
        for (int c = 0; c < 4; c++) acc[n][c] = 0.0f;

    // K b-frag (non-trans, R10/R11-validated): lane>>4 -> +8 n-rows,
    // lane>>3 -> +16B k-offset.  (R12 bug: these two were swapped.)
    const uint32_t bBase = ((lane & 7) + ((lane >> 4) & 1) * 8) * KSTR
                         + ((lane >> 3) & 1) * 16;
    const int r0 = 16 * wid + (lane >> 2);               // S rows (warps 0-3)
    const int r1 = r0 + 8;
    const int pw   = wid - 4;                            // PV warp 0..3
    const int mrow = 16 * pw + (lane >> 2);              // PV rows
    // V b-frag (trans): lanes 8-15 -> k-rows +8 (tile1), lanes 16-23 -> d+8 (tile2)
    const uint32_t vBase = ((lane & 7) + ((lane >> 3) & 1) * 8) * KSTR
                         + ((lane >> 4) & 1) * 16;
    // P a-frag base (non-trans)
    const uint32_t pBase = sb + AT_P0 + (16 * pw + (lane & 15)) * KSTR
                         + (lane >> 4) * 16;

    for (int kt = 0; kt < T_ / 64; kt++) {
        const int buf = kt & 1;
        asm volatile("cp.async.wait_group 0;" ::: "memory");
        __syncthreads();                         // tile kt ready; PV(kt-1) done
        if (kt + 1 < T_ / 64) issue(kt + 1);

        if (wid < 4) {
            // ---- S = Q.K^T : m16n64, 3-term bf16 ----
            float sacc[8][4];
#pragma unroll
            for (int n = 0; n < 8; n++)
#pragma unroll
                for (int c = 0; c < 4; c++) sacc[n][c] = 0.0f;

            const uint32_t kbase = sb + AT_K0 + buf * 2 * KPL + bBase;
#pragma unroll
            for (int k16 = 0; k16 < 4; k16++) {
                uint32_t kb[8][2];
#pragma unroll
                for (int nt = 0; nt < 4; nt++) {
                    uint32_t a0, a1, a2, a3;
                    LDM_X4(a0, a1, a2, a3, kbase + nt * (16 * KSTR) + k16 * 32);
                    kb[2 * nt][0] = a0; kb[2 * nt][1] = a1;
                    kb[2 * nt + 1][0] = a2; kb[2 * nt + 1][1] = a3;
                }
#pragma unroll
                for (int n = 0; n < 8; n++) MMA16816(sacc[n], qh[k16], kb[n]);
#pragma unroll
                for (int n = 0; n < 8; n++) MMA16816(sacc[n], ql[k16], kb[n]);
#pragma unroll
                for (int nt = 0; nt < 4; nt++) {
                    uint32_t a0, a1, a2, a3;
                    LDM_X4(a0, a1, a2, a3,
                           kbase + KPL + nt * (16 * KSTR) + k16 * 32);
                    kb[2 * nt][0] = a0; kb[2 * nt][1] = a1;
                    kb[2 * nt + 1][0] = a2; kb[2 * nt + 1][1] = a3;
                }
#pragma unroll
                for (int n = 0; n < 8; n++) MMA16816(sacc[n], qh[k16], kb[n]);
            }

            // ---- softmax on fragments ----
            float mt0 = sacc[0][0], mt1 = sacc[0][2];
#pragma unroll
            for (int n = 0; n < 8; n++) {
                mt0 = fmaxf(mt0, fmaxf(sacc[n][0], sacc[n][1]));
                mt1 = fmaxf(mt1, fmaxf(sacc[n][2], sacc[n][3]));
            }
            mt0 = fmaxf(mt0, __shfl_xor_sync(0xffffffffu, mt0, 1));
            mt0 = fmaxf(mt0, __shfl_xor_sync(0xffffffffu, mt0, 2));
            mt1 = fmaxf(mt1, __shfl_xor_sync(0xffffffffu, mt1, 1));
            mt1 = fmaxf(mt1, __shfl_xor_sync(0xffffffffu, mt1, 2));
            const float mn0 = fmaxf(m0r, mt0), mn1 = fmaxf(m1r, mt1);
            const float al0 = __expf(m0r - mn0), al1 = __expf(m1r - mn1);

            float ps0 = 0.0f, ps1 = 0.0f;
            const int cb = (lane & 3) * 2;
#pragma unroll
            for (int n = 0; n < 8; n++) {
                const int col = n * 8 + cb;
                const float p00 = __expf(sacc[n][0] - mn0);
                const float p01 = __expf(sacc[n][1] - mn0);
                const float p10 = __expf(sacc[n][2] - mn1);
                const float p11 = __expf(sacc[n][3] - mn1);
                ps0 += p00 + p01; ps1 += p10 + p11;
                // split to bf16 hi/lo and store packed pairs
                uint32_t h0, h1;
                asm("cvt.rn.bf16x2.f32 %0, %1, %2;" : "=r"(h0) : "f"(p01), "f"(p00));
                asm("cvt.rn.bf16x2.f32 %0, %1, %2;" : "=r"(h1) : "f"(p11), "f"(p10));
                const float q00 = p00 - __uint_as_float(h0 << 16);
                const float q01 = p01 - __uint_as_float(h0 & 0xffff0000u);
                const float q10 = p10 - __uint_as_float(h1 << 16);
                const float q11 = p11 - __uint_as_float(h1 & 0xffff0000u);
                uint32_t l0, l1;
                asm("cvt.rn.bf16x2.f32 %0, %1, %2;" : "=r"(l0) : "f"(q01), "f"(q00));
                asm("cvt.rn.bf16x2.f32 %0, %1, %2;" : "=r"(l1) : "f"(q11), "f"(q10));
                char* pp = smc + AT_P0;
                *(uint32_t*)(pp + r0 * KSTR + col * 2)       = h0;
                *(uint32_t*)(pp + r1 * KSTR + col * 2)       = h1;
                *(uint32_t*)(pp + KPL + r0 * KSTR + col * 2) = l0;
                *(uint32_t*)(pp + KPL + r1 * KSTR + col * 2) = l1;
            }
            ps0 += __shfl_xor_sync(0xffffffffu, ps0, 1);
            ps0 += __shfl_xor_sync(0xffffffffu, ps0, 2);
            ps1 += __shfl_xor_sync(0xffffffffu, ps1, 1);
            ps1 += __shfl_xor_sync(0xffffffffu, ps1, 2);
            l0r = l0r * al0 + ps0;  m0r = mn0;
            l1r = l1r * al1 + ps1;  m1r = mn1;
            if ((lane & 3) == 0) {
                alphaF[r0] = al0;
                alphaF[r1] = al1;
                if (kt == T_ / 64 - 1) {
                    linv[r0] = 1.0f / l0r;
                    linv[r1] = 1.0f / l1r;
                }
            }
        }
        __syncthreads();                         // P, alphaF ready

        if (wid >= 4) {
            // ---- rescale ----
            const float a0 = alphaF[mrow];
            const float a1 = alphaF[mrow + 8];
#pragma unroll
            for (int n = 0; n < 8; n++) {
                acc[n][0] *= a0; acc[n][1] *= a0;
                acc[n][2] *= a1; acc[n][3] *= a1;
            }
            // ---- O += P.V (3 terms) ----
            const uint32_t vb = sb + AT_V0 + buf * 2 * KPL + vBase;
#pragma unroll
            for (int k16 = 0; k16 < 4; k16++) {
                uint32_t ph[4], pl[4];
                LDM_X4(ph[0], ph[1], ph[2], ph[3], pBase + k16 * 32);
                LDM_X4(pl[0], pl[1], pl[2], pl[3], pBase + KPL + k16 * 32);
#pragma unroll
                for (int d16 = 0; d16 < 4; d16++) {
                    uint32_t vh[4], vl[4];
                    LDM_X4_T(vh[0], vh[1], vh[2], vh[3],
                             vb + k16 * (16 * KSTR) + d16 * 32);
                    LDM_X4_T(vl[0], vl[1], vl[2], vl[3],
                             vb + KPL + k16 * (16 * KSTR) + d16 * 32);
                    uint32_t bvh0[2] = { vh[0], vh[1] }, bvh1[2] = { vh[2], vh[3] };
                    uint32_t bvl0[2] = { vl[0], vl[1] }, bvl1[2] = { vl[2], vl[3] };
                    MMA16816(acc[2 * d16],     ph, bvh0);
                    MMA16816(acc[2 * d16 + 1], ph, bvh1);
                    MMA16816(acc[2 * d16],     ph, bvl0);
                    MMA16816(acc[2 * d16 + 1], ph, bvl1);
                    MMA16816(acc[2 * d16],     pl, bvh0);
                    MMA16816(acc[2 * d16 + 1], pl, bvh1);
                }
            }
        }
    }

    // ---- epilogue: O * linv, write [BT][C] (warps 4-7) ----
    if (wid >= 4) {
        const int b = bh >> 4, h = bh & 15;
        const float li0 = linv[mrow];
        const float li1 = linv[mrow + 8];
        float* base0 = Y + ((size_t)b * T_ + qt * 64 + mrow) * C_ + h * D_;
        float* base1 = base0 + (size_t)8 * C_;
        const int cb = (lane & 3) * 2;
#pragma unroll
        for (int n = 0; n < 8; n++) {
            *(float2*)(base0 + n * 8 + cb) =
                make_float2(acc[n][0] * li0, acc[n][1] * li0);
            *(float2*)(base1 + n * 8 + cb) =
                make_float2(acc[n][2] * li1, acc[n][3] * li1);
        }
    }
}

// ==========================================================================
extern "C" void kernel_launch(void* const* d_in, const int* in_sizes, int n_in,
                              void* d_out, int out_size)
{
    const float* x   = (const float*)d_in[0];
    const float* Wq  = (const float*)d_in[1];
    const float* Wk  = (const float*)d_in[2];
    const float* Wv  = (const float*)d_in[3];
    const float* Wo  = (const float*)d_in[4];
    const float* sqk = (const float*)d_in[5];
    float* out = (float*)d_out;

    static float *q = nullptr, *k, *v, *qn, *kn, *vn, *att;
    static __nv_bfloat16 *xs, *ws, *as;
    static bool init_done = false;
    if (!init_done) {
        cudaGetSymbolAddress((void**)&q,   g_q);
        cudaGetSymbolAddress((void**)&k,   g_k);
        cudaGetSymbolAddress((void**)&v,   g_v);
        cudaGetSymbolAddress((void**)&qn,  g_qn);
        cudaGetSymbolAddress((void**)&kn,  g_kn);
        cudaGetSymbolAddress((void**)&vn,  g_vn);
        cudaGetSymbolAddress((void**)&att, g_att);
        cudaGetSymbolAddress((void**)&xs,  g_xs);
        cudaGetSymbolAddress((void**)&ws,  g_ws);
        cudaGetSymbolAddress((void**)&as,  g_as);
        cudaFuncSetAttribute(attn_kernel,
                             cudaFuncAttributeMaxDynamicSharedMemorySize, AT_SM);
        cudaFuncSetAttribute(gemm_hmma_kernel,
                             cudaFuncAttributeMaxDynamicSharedMemorySize, GSMEM);
        init_done = true;
    }

    // split x and the 4 weight matrices to bf16 hi/lo planes
    split_kernel<<<AELEM / 4 / 256, 256>>>((const float4*)x, (uint2*)xs,
                                           (uint2*)(xs + AELEM));
    split_w_kernel<<<dim3(WELEM / 4 / 256, 1, 4), 256>>>(Wq, Wk, Wv, Wo, ws);

    // QKV projections on HMMA (bf16x3)
    gemm_hmma_kernel<<<dim3(8, 32, 3), 256, GSMEM>>>(xs, ws, q, k, v);

    // RoPE + norm; Q/K/V emitted as bf16 hi/lo planes
    rope_norm_kernel<<<(BT_ * H_) / 8, 256>>>(
        q, k, v, sqk, (__nv_bfloat16*)qn, (__nv_bfloat16*)kn, (__nv_bfloat16*)vn);

    // Flash attention (S and PV both on HMMA bf16x3)
    attn_kernel<<<dim3(T_ / 64, BH_), 256, AT_SM>>>(
        (const __nv_bfloat16*)qn, (const __nv_bfloat16*)kn,
        (const __nv_bfloat16*)vn, att);

    // split attention output, then Wo projection on HMMA
    split_kernel<<<AELEM / 4 / 256, 256>>>((const float4*)att, (uint2*)as,
                                           (uint2*)(as + AELEM));
    gemm_hmma_kernel<<<dim3(8, 32, 1), 256, GSMEM>>>(as, ws + (size_t)3 * 2 * WELEM,
                                                     out, out, out);
}